// round 6
// baseline (speedup 1.0000x reference)
#include <cuda_runtime.h>

#define NN   128
#define FIN  512
#define EE   128
#define H1D  256
#define H2D  128
#define TPB  512

typedef unsigned long long ull;

__device__ __forceinline__ ull ffma2(ull a, ull b, ull c){
    ull d;
    asm("fma.rn.f32x2 %0, %1, %2, %3;" : "=l"(d) : "l"(a), "l"(b), "l"(c));
    return d;
}
__device__ __forceinline__ ull packff(float x){
    ull d; asm("mov.b64 %0, {%1, %2};" : "=l"(d) : "f"(x), "f"(x)); return d;
}

// ---------------- persistent device state ----------------------------------
__device__ float g_P[NN*EE];
__device__ float g_feat0[NN*EE];
__device__ float g_A0[NN*H1D];
__device__ float g_G0[NN*H1D];
__device__ float g_G[NN*H1D];
__device__ float g_feat[NN*EE];
__device__ int   g_cand[NN*4];
__device__ int   g_ccnt[NN];
__device__ int   g_upd[NN];
__device__ ull   g_mL[NN], g_mH[NN];
__device__ int   g_group[NN*4];
__device__ int   g_gc[NN];
__device__ int   g_ngroups;

// ---------------- initA: 4 nodes per block ----------------------------------
__global__ void initA_kernel(const float* __restrict__ fo, const float* __restrict__ We,
                             const float* __restrict__ be, const float* __restrict__ adj)
{
    __shared__ float fos[4][FIN];
    __shared__ unsigned bal[4][4];
    int m = threadIdx.x >> 7;
    int e = threadIdx.x & 127;
    int i = blockIdx.x*4 + m;
    ((float4*)fos[m])[e] = ((const float4*)(fo + i*FIN))[e];
    unsigned b = __ballot_sync(0xffffffffu, adj[i*NN + e] != 0.0f);
    if ((e & 31) == 0) bal[m][e >> 5] = b;
    __syncthreads();

    float s = 0.f;
    #pragma unroll 16
    for (int f = 0; f < FIN; f++) s += fos[m][f] * We[f*EE + e];
    g_P[i*EE+e] = s;
    float f0 = fmaxf(s + be[e], 0.f);
    g_feat0[i*EE+e] = f0;
    g_feat [i*EE+e] = f0;

    if (e == 0) {
        g_upd[i] = 0;
        int c = 0; ull ml = 0, mh = 0;
        if (i < 64) ml |= 1ull << i; else mh |= 1ull << (i-64);
        for (int wq = 0; wq < 4; wq++){
            unsigned bb = bal[m][wq];
            while (bb){
                int bit = __ffs(bb) - 1; bb &= bb - 1;
                int vtx = wq*32 + bit;
                if (c < 4) g_cand[i*4 + c] = vtx;
                c++;
                if (vtx < 64) ml |= 1ull << vtx; else mh |= 1ull << (vtx-64);
            }
        }
        if (c > 3) c = 3;
        g_ccnt[i] = c;
        g_mL[i] = ml; g_mH[i] = mh;
    }
}

// ---------------- initB: A0/G0/G -------------------------------------------
__global__ void initB_kernel(const float* __restrict__ W1)
{
    __shared__ float fs[EE];
    int i = blockIdx.x, j = threadIdx.x;
    if (j < EE) fs[j] = g_feat0[i*EE + j];
    __syncthreads();
    float st = 0.f, sb = 0.f;
    #pragma unroll 16
    for (int k = 0; k < EE; k++){
        float f = fs[k];
        st += f * W1[k*H1D + j];
        sb += f * W1[(EE+k)*H1D + j];
    }
    g_A0[i*H1D+j] = st;
    g_G0[i*H1D+j] = sb;
    g_G [i*H1D+j] = sb;
}

// ---------------- scheduler ------------------------------------------------
__global__ void sched_kernel()
{
    __shared__ ull mL[NN], mH[NN];
    __shared__ int lvl[NN], hist[NN], gb_[NN];
    int t = threadIdx.x;
    mL[t] = g_mL[t]; mH[t] = g_mH[t]; hist[t] = 0;
    #pragma unroll
    for (int q = 0; q < 4; q++) g_group[t*4 + q] = -1;
    __syncthreads();

    if (t < 32){
        for (int i = 0; i < NN; i++){
            ull aL = mL[i], aH = mH[i];
            int best = -1;
            #pragma unroll
            for (int q = 0; q < 4; q++){
                int j = t + q*32;
                if (j < i && (((mL[j]&aL) | (mH[j]&aH)) != 0ull))
                    best = max(best, lvl[j]);
            }
            #pragma unroll
            for (int off = 16; off; off >>= 1)
                best = max(best, __shfl_xor_sync(0xffffffffu, best, off));
            if (t == 0) lvl[i] = best + 1;
            __syncwarp();
        }
    }
    __syncthreads();

    int L = lvl[t];
    atomicAdd(&hist[L], 1);
    __syncthreads();
    if (t == 0){
        int gb = 0;
        for (int l = 0; l < NN; l++){ gb_[l] = gb; gb += (hist[l] + 3) >> 2; }
        g_ngroups = gb;
    }
    __syncthreads();
    int r = 0;
    for (int j = 0; j < NN; j++) r += (j < t && lvl[j] == L);
    int grp = gb_[L] + (r >> 2), slot = r & 3;
    g_group[grp*4 + slot] = t;
    if (slot == 0) g_gc[grp] = min(4, hist[L] - r);
}

// ---------------- S2 template: NPAIR = compacted pair count -----------------
template<int NPAIR>
__device__ __forceinline__ void s2_compute(const ull* __restrict__ h1P,
                                           float2* __restrict__ part,
                                           const float (&w2a)[32], const float (&w2b)[32],
                                           int kslab, int j0)
{
    ull accA[NPAIR], accB[NPAIR];
    #pragma unroll
    for (int p = 0; p < NPAIR; p++){ accA[p] = 0ull; accB[p] = 0ull; }
    #pragma unroll
    for (int kk = 0; kk < 32; kk++){
        int k = kslab*32 + kk;
        ull wpa = packff(w2a[kk]), wpb = packff(w2b[kk]);
        #pragma unroll
        for (int p = 0; p < NPAIR; p++){
            ull hp = h1P[p*256 + k];
            accA[p] = ffma2(hp, wpa, accA[p]);
            accB[p] = ffma2(hp, wpb, accB[p]);
        }
    }
    #pragma unroll
    for (int p = 0; p < NPAIR; p++){
        float2 fa, fb;
        asm("mov.b64 {%0,%1}, %2;" : "=f"(fa.x), "=f"(fa.y) : "l"(accA[p]));
        asm("mov.b64 {%0,%1}, %2;" : "=f"(fb.x), "=f"(fb.y) : "l"(accB[p]));
        part[(p*8 + kslab)*128 + j0]     = fa;
        part[(p*8 + kslab)*128 + j0 + 1] = fb;
    }
}

// ---------------- main wave-parallel rollout: ONE CTA -----------------------
extern __shared__ float sm[];

__global__ void __launch_bounds__(TPB, 1) main_kernel(
    const float* __restrict__ W1, const float* __restrict__ W2,
    const float* __restrict__ b1, const float* __restrict__ b2,
    const float* __restrict__ wlk, const float* __restrict__ blk,
    const float* __restrict__ wact, const float* __restrict__ bact,
    const float* __restrict__ be, float* __restrict__ out)
{
    // dynamic smem layout
    float* base_ = sm;
    float*  w1s  = base_;                base_ += 32768;   // W1_top resident [128k][256j]
    float*  uni  = base_;                base_ += 20480;   // part(16384)+h1P(4096); dual/dualB alias
    float*  a_   = base_;                base_ += 1024;
    float*  curx = base_;                base_ += 512;
    float*  selP = base_;                base_ += 512;
    float*  Pis  = base_;                base_ += 512;
    float*  b1s  = base_;                base_ += 256;
    float*  b2s  = base_;                base_ += 128;
    float*  wlks = base_;                base_ += 128;
    float*  wa0  = base_;                base_ += 128;
    float*  wa1  = base_;                base_ += 128;
    float*  bes  = base_;                base_ += 128;

    float2* part = (float2*)uni;                 // [pair][ks][j]  (16384 floats)
    ull*    h1P  = (ull*)(uni + 16384);          // [pair][256k]   (4096 floats)
    float*  dual = uni;                          // aliases part   (8192 floats)
    float*  dualB= uni + 8192;                   // aliases part   (8192 floats)

    __shared__ float s_lk[16], s_a0[16], s_a1[16];
    __shared__ float s_cntv[4], s_den[4];
    __shared__ int   s_alive[4][3], s_na[4], s_done[4], s_vsel[4], s_at[4];
    __shared__ int   s_sel[4], s_needgi[4], s_gdirty[4], s_nid[4];
    __shared__ int   s_slotmap[16];
    __shared__ int   s_cont, s_needB, s_flush, s_P, s_nslots;
    __shared__ float s_blk, s_ba0, s_ba1;

    const int tid  = threadIdx.x;
    const int w    = tid >> 5;
    const int lane = tid & 31;
    const int kslab = w >> 1, jh = w & 1;
    const int j0 = jh*64 + lane*2;

    if (tid < H1D) b1s[tid] = b1[tid];
    if (tid < H2D){ b2s[tid]=b2[tid]; wlks[tid]=wlk[tid];
                    wa0[tid]=wact[2*tid]; wa1[tid]=wact[2*tid+1]; }
    if (tid < EE)  bes[tid] = be[tid];
    if (tid == 0){ s_blk=blk[0]; s_ba0=bact[0]; s_ba1=bact[1]; }

    // W1_top -> smem (rows 0..127 of W1, contiguous)
    #pragma unroll
    for (int q = 0; q < 16; q++)
        ((float4*)w1s)[q*TPB + tid] = ((const float4*)W1)[q*TPB + tid];

    float w2a[32], w2b[32];
    #pragma unroll
    for (int kk = 0; kk < 32; kk++){
        float2 v = *(const float2*)(W2 + (kslab*32+kk)*H2D + j0);
        w2a[kk] = v.x; w2b[kk] = v.y;
    }
    int ngroups = g_ngroups;
    __syncthreads();

    for (int g = 0; g < ngroups; g++){
        // ---- wave init (single thread: s_na visible to slotmap build) ----
        if (tid == 0){
            int ns = 0;
            for (int m = 0; m < 4; m++){
                int nid = g_group[g*4 + m];
                s_nid[m] = nid;
                if (nid >= 0){
                    int c = g_ccnt[nid]; s_na[m] = c;
                    for (int q = 0; q < c; q++) s_alive[m][q] = g_cand[nid*4 + q];
                    s_done[m] = 0; s_cntv[m] = 0.f; s_gdirty[m] = 0; s_sel[m] = 0;
                    if (c > 0) for (int r = 0; r <= c; r++) s_slotmap[ns++] = m*4 + r;
                } else { s_na[m] = 0; s_done[m] = 1; s_gdirty[m] = 0; s_sel[m] = 0; }
            }
            s_nslots = ns; s_P = (ns + 1) >> 1; s_cont = (ns > 0);
        }
        #pragma unroll
        for (int h = 0; h < 2; h++){
            int idx = h*512 + tid, m = idx >> 8, j = idx & 255;
            int nid = g_group[g*4 + m];
            a_[m*256 + j] = (nid >= 0) ? g_A0[nid*H1D + j] : 0.f;
        }
        {
            int m = tid >> 7, e = tid & 127;
            int nid = g_group[g*4 + m];
            curx[m*128+e] = 0.f; selP[m*128+e] = 0.f;
            Pis[m*128+e] = (nid >= 0) ? g_P[nid*EE + e] : 0.f;
        }
        __syncthreads();

        // ---- step loop ----
        for (int step = 0; step < 3; step++){
            if (!s_cont) break;
            int nslots = s_nslots, npair = s_P;

            // S1: compacted h1 pairs
            {
                int k = tid & 255, hi = tid >> 8;
                #pragma unroll
                for (int pp = 0; pp < 4; pp++){
                    int p = hi*4 + pp;
                    if (p >= npair) break;
                    float v2[2];
                    #pragma unroll
                    for (int h2 = 0; h2 < 2; h2++){
                        int cs = p*2 + h2;
                        float val = 0.f;
                        if (cs < nslots){
                            int orig = s_slotmap[cs];
                            int m = orig >> 2, r = orig & 3;
                            float bb = a_[m*256 + k] + b1s[k];
                            if (r < s_na[m]){
                                int v = s_alive[m][r];
                                float gg = (v > 0) ? g_G[v*H1D + k] : 0.f;  // `if v>0` quirk
                                val = fmaxf(bb + gg, 0.f);
                            } else val = fmaxf(bb, 0.f);                    // sentinel
                        }
                        v2[h2] = val;
                    }
                    ull pk; asm("mov.b64 %0, {%1,%2};" : "=l"(pk) : "f"(v2[0]), "f"(v2[1]));
                    h1P[p*256 + k] = pk;
                }
            }
            __syncthreads();

            // S2 (compacted pair count)
            switch (npair){
                case 1:  s2_compute<1>(h1P, part, w2a, w2b, kslab, j0); break;
                case 2:  s2_compute<2>(h1P, part, w2a, w2b, kslab, j0); break;
                case 3:  s2_compute<3>(h1P, part, w2a, w2b, kslab, j0); break;
                case 4:  s2_compute<4>(h1P, part, w2a, w2b, kslab, j0); break;
                case 5:  s2_compute<5>(h1P, part, w2a, w2b, kslab, j0); break;
                case 6:  s2_compute<6>(h1P, part, w2a, w2b, kslab, j0); break;
                case 7:  s2_compute<7>(h1P, part, w2a, w2b, kslab, j0); break;
                default: s2_compute<8>(h1P, part, w2a, w2b, kslab, j0); break;
            }
            __syncthreads();

            // S3: warp per compacted slot
            if (w < nslots){
                int orig = s_slotmap[w];
                int pair = w >> 1, el = w & 1;
                float lk = 0.f, p0 = 0.f, p1 = 0.f;
                #pragma unroll
                for (int q = 0; q < 4; q++){
                    int j = lane + q*32;
                    float ss = b2s[j];
                    #pragma unroll
                    for (int ks = 0; ks < 8; ks++){
                        float2 vv = part[(pair*8 + ks)*128 + j];
                        ss += el ? vv.y : vv.x;
                    }
                    float h = fmaxf(ss, 0.f);
                    lk += h*wlks[j]; p0 += h*wa0[j]; p1 += h*wa1[j];
                }
                #pragma unroll
                for (int off = 16; off; off >>= 1){
                    lk += __shfl_xor_sync(0xffffffffu, lk, off);
                    p0 += __shfl_xor_sync(0xffffffffu, p0, off);
                    p1 += __shfl_xor_sync(0xffffffffu, p1, off);
                }
                if (lane == 0){ s_lk[orig]=lk+s_blk; s_a0[orig]=p0+s_ba0; s_a1[orig]=p1+s_ba1; }
            }
            __syncthreads();

            // S4a: per-node decision
            if (tid < 4){
                int m = tid; s_sel[m] = 0;
                if (!s_done[m] && s_na[m] > 0){
                    int na = s_na[m], bse = m*4;
                    float best = -3.4028235e38f; int bi = -1;
                    for (int r = 0; r < na; r++)
                        if (s_lk[bse+r] > best){ best = s_lk[bse+r]; bi = r; }
                    if (s_lk[bse+na] > best){
                        s_done[m] = 1;
                    } else {
                        int v  = s_alive[m][bi];
                        int at = (s_a1[bse+bi] > s_a0[bse+bi]) ? 1 : 0;
                        s_vsel[m] = v; s_at[m] = at; s_sel[m] = 1;
                        s_den[m]  = s_cntv[m] + (float)at + 1.0f;
                        s_cntv[m] += (float)at;
                        for (int q = bi; q < na-1; q++) s_alive[m][q] = s_alive[m][q+1];
                        s_na[m] = na - 1;
                        int nid = s_nid[m];
                        int ng = 0;
                        for (int q = 0; q < na-1; q++) if (s_alive[m][q] == nid) ng = 1;
                        s_needgi[m] = ng;
                        s_gdirty[m] = (v == nid) ? 0 : 1;
                        g_upd[nid] = 1; g_upd[v] = 1;
                    }
                }
            }
            __syncthreads();

            // S4b + rebuild compacted slotmap
            {
                if (tid == 0){
                    int ns = 0, nB = 0;
                    for (int m = 0; m < 4; m++){
                        if (!s_done[m] && s_na[m] > 0)
                            for (int r = 0; r <= s_na[m]; r++) s_slotmap[ns++] = m*4 + r;
                        if (s_sel[m] && s_needgi[m]) nB = 1;
                    }
                    s_nslots = ns; s_P = (ns + 1) >> 1;
                    s_cont = (ns > 0); s_needB = nB;
                }
                int m = tid >> 7, e = tid & 127;
                if (s_sel[m]){
                    int nid = s_nid[m], v = s_vsel[m];
                    float atf = (float)s_at[m], denom = s_den[m];
                    float pv = g_P[v*EE + e], pi = Pis[m*128 + e];
                    float nx = fmaxf((selP[m*128+e] + atf*pv + pi)/denom + bes[e], 0.f);
                    if (s_at[m]) selP[m*128+e] += pv;
                    float f0v = g_feat0[v*EE + e];
                    g_feat[v*EE + e] = f0v;
                    float fx = (v == nid) ? f0v : nx;
                    g_feat[nid*EE + e] = fx;
                    curx[m*128 + e] = fx;
                }
                #pragma unroll
                for (int h = 0; h < 2; h++){
                    int idx = h*512 + tid, mm2 = idx >> 8, jj = idx & 255;
                    if (s_sel[mm2]) g_G[s_vsel[mm2]*H1D + jj] = g_G0[s_vsel[mm2]*H1D + jj];
                }
            }
            __syncthreads();
            if (!s_cont) break;
            if (step >= 2) break;          // flush covers final G[i]; a_ dead after

            // S5: batched a = curx @ W1_top from SMEM (+ G[i] bottom LDG stream)
            {
                int jg = tid & 63, ks = tid >> 6;
                const float* bw = w1s + (ks*16)*H1D + jg*4;
                float4 a0 = make_float4(0,0,0,0), a1 = a0, a2 = a0, a3 = a0;
                #pragma unroll
                for (int kk = 0; kk < 16; kk++){
                    float4 wr = *(const float4*)(bw + kk*H1D);
                    float c0 = curx[0*128 + ks*16 + kk];
                    float c1 = curx[1*128 + ks*16 + kk];
                    float c2 = curx[2*128 + ks*16 + kk];
                    float c3 = curx[3*128 + ks*16 + kk];
                    a0.x += c0*wr.x; a0.y += c0*wr.y; a0.z += c0*wr.z; a0.w += c0*wr.w;
                    a1.x += c1*wr.x; a1.y += c1*wr.y; a1.z += c1*wr.z; a1.w += c1*wr.w;
                    a2.x += c2*wr.x; a2.y += c2*wr.y; a2.z += c2*wr.z; a2.w += c2*wr.w;
                    a3.x += c3*wr.x; a3.y += c3*wr.y; a3.z += c3*wr.z; a3.w += c3*wr.w;
                }
                float4 e0, e1, e2, e3;
                if (s_needB){
                    const float* bwB = W1 + (EE + ks*16)*H1D + jg*4;
                    e0 = make_float4(0,0,0,0); e1 = e0; e2 = e0; e3 = e0;
                    #pragma unroll
                    for (int kk = 0; kk < 16; kk++){
                        float4 wr = *(const float4*)(bwB + kk*H1D);
                        float c0 = curx[0*128 + ks*16 + kk];
                        float c1 = curx[1*128 + ks*16 + kk];
                        float c2 = curx[2*128 + ks*16 + kk];
                        float c3 = curx[3*128 + ks*16 + kk];
                        e0.x += c0*wr.x; e0.y += c0*wr.y; e0.z += c0*wr.z; e0.w += c0*wr.w;
                        e1.x += c1*wr.x; e1.y += c1*wr.y; e1.z += c1*wr.z; e1.w += c1*wr.w;
                        e2.x += c2*wr.x; e2.y += c2*wr.y; e2.z += c2*wr.z; e2.w += c2*wr.w;
                        e3.x += c3*wr.x; e3.y += c3*wr.y; e3.z += c3*wr.z; e3.w += c3*wr.w;
                    }
                }
                __syncthreads();   // part/h1P dead -> safe to write dual/dualB aliases
                *(float4*)(dual + (0*8 + ks)*H1D + jg*4) = a0;
                *(float4*)(dual + (1*8 + ks)*H1D + jg*4) = a1;
                *(float4*)(dual + (2*8 + ks)*H1D + jg*4) = a2;
                *(float4*)(dual + (3*8 + ks)*H1D + jg*4) = a3;
                if (s_needB){
                    *(float4*)(dualB + (0*8 + ks)*H1D + jg*4) = e0;
                    *(float4*)(dualB + (1*8 + ks)*H1D + jg*4) = e1;
                    *(float4*)(dualB + (2*8 + ks)*H1D + jg*4) = e2;
                    *(float4*)(dualB + (3*8 + ks)*H1D + jg*4) = e3;
                }
            }
            __syncthreads();
            // reduce
            {
                #pragma unroll
                for (int h = 0; h < 2; h++){
                    int idx = h*512 + tid, m = idx >> 8, j = idx & 255;
                    float ssum = 0.f;
                    #pragma unroll
                    for (int ks = 0; ks < 8; ks++) ssum += dual[(m*8 + ks)*H1D + j];
                    a_[m*256 + j] = ssum;
                    if (s_needB && s_sel[m] && s_needgi[m]){
                        float sb = 0.f;
                        #pragma unroll
                        for (int ks = 0; ks < 8; ks++) sb += dualB[(m*8 + ks)*H1D + j];
                        g_G[s_nid[m]*H1D + j] = sb;
                    }
                }
                if (tid < 4 && s_sel[tid] && s_needgi[tid]) s_gdirty[tid] = 0;
            }
            __syncthreads();
        } // steps

        // ---- flush stale G[i] rows (bottom stream, LDG) ----
        if (tid == 0){
            int f = 0;
            for (int m = 0; m < 4; m++) if (s_gdirty[m]) f = 1;
            s_flush = f;
        }
        __syncthreads();
        if (s_flush){
            {
                int jg = tid & 63, ks = tid >> 6;
                const float* bwB = W1 + (EE + ks*16)*H1D + jg*4;
                float4 e0 = make_float4(0,0,0,0), e1 = e0, e2 = e0, e3 = e0;
                #pragma unroll
                for (int kk = 0; kk < 16; kk++){
                    float4 wr = *(const float4*)(bwB + kk*H1D);
                    float c0 = curx[0*128 + ks*16 + kk];
                    float c1 = curx[1*128 + ks*16 + kk];
                    float c2 = curx[2*128 + ks*16 + kk];
                    float c3 = curx[3*128 + ks*16 + kk];
                    e0.x += c0*wr.x; e0.y += c0*wr.y; e0.z += c0*wr.z; e0.w += c0*wr.w;
                    e1.x += c1*wr.x; e1.y += c1*wr.y; e1.z += c1*wr.z; e1.w += c1*wr.w;
                    e2.x += c2*wr.x; e2.y += c2*wr.y; e2.z += c2*wr.z; e2.w += c2*wr.w;
                    e3.x += c3*wr.x; e3.y += c3*wr.y; e3.z += c3*wr.z; e3.w += c3*wr.w;
                }
                *(float4*)(dual + (0*8 + ks)*H1D + jg*4) = e0;
                *(float4*)(dual + (1*8 + ks)*H1D + jg*4) = e1;
                *(float4*)(dual + (2*8 + ks)*H1D + jg*4) = e2;
                *(float4*)(dual + (3*8 + ks)*H1D + jg*4) = e3;
            }
            __syncthreads();
            #pragma unroll
            for (int h = 0; h < 2; h++){
                int idx = h*512 + tid, m = idx >> 8, j = idx & 255;
                if (s_gdirty[m]){
                    float sb = 0.f;
                    #pragma unroll
                    for (int ks = 0; ks < 8; ks++) sb += dual[(m*8 + ks)*H1D + j];
                    g_G[s_nid[m]*H1D + j] = sb;
                }
            }
            __syncthreads();
        }
    } // groups

    // output
    __syncthreads();
    for (int t = tid; t < NN*EE; t += TPB)
        out[t] = g_upd[t >> 7] ? g_feat[t] : 0.f;
}

// ---------------- launch ----------------------------------------------------
static const int DYN_SMEM = (32768 + 20480 + 1024 + 512*3 + 256 + 128*5)
                            * (int)sizeof(float);   // 226816 B

extern "C" void kernel_launch(void* const* d_in, const int* in_sizes, int n_in,
                              void* d_out, int out_size)
{
    const float* adj = (const float*)d_in[0];
    const float* fo  = (const float*)d_in[1];
    // d_in[2] = labels (unused)
    const float* We  = (const float*)d_in[3];
    const float* be  = (const float*)d_in[4];
    const float* W1  = (const float*)d_in[5];
    const float* b1  = (const float*)d_in[6];
    const float* W2  = (const float*)d_in[7];
    const float* b2  = (const float*)d_in[8];
    const float* wlk = (const float*)d_in[9];
    const float* blk = (const float*)d_in[10];
    const float* wac = (const float*)d_in[11];
    const float* bac = (const float*)d_in[12];
    float* out = (float*)d_out;

    cudaFuncSetAttribute(main_kernel, cudaFuncAttributeMaxDynamicSharedMemorySize, DYN_SMEM);

    initA_kernel<<<32, 512>>>(fo, We, be, adj);
    initB_kernel<<<NN, H1D>>>(W1);
    sched_kernel<<<1, 128>>>();
    main_kernel<<<1, TPB, DYN_SMEM>>>(W1, W2, b1, b2, wlk, blk, wac, bac, be, out);
}

// round 7
// speedup vs baseline: 4.8319x; 4.8319x over previous
#include <cuda_runtime.h>

#define NN   128
#define FIN  512
#define EE   128
#define H1D  256
#define H2D  128
#define TPB  512

typedef unsigned long long ull;

__device__ __forceinline__ ull ffma2(ull a, ull b, ull c){
    ull d;
    asm("fma.rn.f32x2 %0, %1, %2, %3;" : "=l"(d) : "l"(a), "l"(b), "l"(c));
    return d;
}
__device__ __forceinline__ ull packff(float x){
    ull d; asm("mov.b64 %0, {%1, %2};" : "=l"(d) : "f"(x), "f"(x)); return d;
}
__device__ __forceinline__ int ld_acquire(const int* p){
    int v;
    asm volatile("ld.acquire.gpu.global.b32 %0, [%1];" : "=r"(v) : "l"(p) : "memory");
    return v;
}
__device__ __forceinline__ void st_release(int* p, int v){
    asm volatile("st.release.gpu.global.b32 [%0], %1;" :: "l"(p), "r"(v) : "memory");
}

// ---------------- persistent device state ----------------------------------
__device__ float g_P[NN*EE];
__device__ float g_feat0[NN*EE];
__device__ float g_A0[NN*H1D];
__device__ float g_G0[NN*H1D];
__device__ float g_G[NN*H1D];
__device__ float g_feat[NN*EE];
__device__ int   g_cand[NN*4];
__device__ int   g_ccnt[NN];
__device__ int   g_upd[NN];
__device__ ull   g_mL[NN], g_mH[NN];
__device__ int   g_done[NN];

// ---------------- initA: 4 nodes per block (validated R5) -------------------
__global__ void initA_kernel(const float* __restrict__ fo, const float* __restrict__ We,
                             const float* __restrict__ be, const float* __restrict__ adj)
{
    __shared__ float fos[4][FIN];
    __shared__ unsigned bal[4][4];
    int m = threadIdx.x >> 7;
    int e = threadIdx.x & 127;
    int i = blockIdx.x*4 + m;
    ((float4*)fos[m])[e] = ((const float4*)(fo + i*FIN))[e];
    unsigned b = __ballot_sync(0xffffffffu, adj[i*NN + e] != 0.0f);
    if ((e & 31) == 0) bal[m][e >> 5] = b;
    __syncthreads();

    float s = 0.f;
    #pragma unroll 16
    for (int f = 0; f < FIN; f++) s += fos[m][f] * We[f*EE + e];
    g_P[i*EE+e] = s;
    float f0 = fmaxf(s + be[e], 0.f);
    g_feat0[i*EE+e] = f0;
    g_feat [i*EE+e] = f0;

    if (e == 0) {
        g_upd[i]  = 0;
        g_done[i] = 0;
        int c = 0; ull ml = 0, mh = 0;
        if (i < 64) ml |= 1ull << i; else mh |= 1ull << (i-64);
        for (int wq = 0; wq < 4; wq++){
            unsigned bb = bal[m][wq];
            while (bb){
                int bit = __ffs(bb) - 1; bb &= bb - 1;
                int vtx = wq*32 + bit;
                if (c < 4) g_cand[i*4 + c] = vtx;
                c++;
                if (vtx < 64) ml |= 1ull << vtx; else mh |= 1ull << (vtx-64);
            }
        }
        if (c > 3) c = 3;                              // K=3 -> <=3 distinct
        g_ccnt[i] = c;
        g_mL[i] = ml; g_mH[i] = mh;
    }
}

// ---------------- initB: A0/G0/G -------------------------------------------
__global__ void initB_kernel(const float* __restrict__ W1)
{
    __shared__ float fs[EE];
    int i = blockIdx.x, j = threadIdx.x;
    if (j < EE) fs[j] = g_feat0[i*EE + j];
    __syncthreads();
    float st = 0.f, sb = 0.f;
    #pragma unroll 16
    for (int k = 0; k < EE; k++){
        float f = fs[k];
        st += f * W1[k*H1D + j];
        sb += f * W1[(EE+k)*H1D + j];
    }
    g_A0[i*H1D+j] = st;
    g_G0[i*H1D+j] = sb;
    g_G [i*H1D+j] = sb;
}

// ---------------- dataflow rollout: 128 CTAs, one node each -----------------
__global__ void __launch_bounds__(TPB, 1) dataflow_kernel(
    const float* __restrict__ W1, const float* __restrict__ W2,
    const float* __restrict__ b1, const float* __restrict__ b2,
    const float* __restrict__ wlk, const float* __restrict__ blk,
    const float* __restrict__ wact, const float* __restrict__ bact,
    const float* __restrict__ be)
{
    __shared__ __align__(16) float a_[H1D];
    __shared__ __align__(16) float dual[8*H1D];
    __shared__ __align__(16) float h1T[H1D*4];
    __shared__ __align__(16) float2 part01[8*H2D];   // also dualB alias (2048 floats)
    __shared__ __align__(16) float2 part23[8*H2D];
    __shared__ float curx[EE], selP[EE];
    __shared__ float b1s[H1D], b2s[H2D], wlks[H2D], wa0[H2D], wa1[H2D], bes[EE];
    __shared__ float s_lk[4], s_a0[4], s_a1[4];
    __shared__ float s_cnt, s_denom, s_blk, s_ba0, s_ba1;
    __shared__ int   s_alive[4];
    __shared__ int   s_na, s_vsel, s_at, s_done, s_needgi, s_gdirty;

    const int i    = blockIdx.x;
    const int tid  = threadIdx.x;
    const int w    = tid >> 5;
    const int lane = tid & 31;
    const int kslab = w >> 1, jh = w & 1;
    const int j0 = jh*64 + lane*2;

    // constants + W2 registers (no dependency on other nodes)
    if (tid < H1D) b1s[tid] = b1[tid];
    if (tid < H2D){ b2s[tid]=b2[tid]; wlks[tid]=wlk[tid];
                    wa0[tid]=wact[2*tid]; wa1[tid]=wact[2*tid+1]; }
    if (tid < EE)  bes[tid] = be[tid];
    if (tid == 0){ s_blk=blk[0]; s_ba0=bact[0]; s_ba1=bact[1]; }

    float w2a[32], w2b[32];
    #pragma unroll
    for (int kk = 0; kk < 32; kk++){
        float2 v = *(const float2*)(W2 + (kslab*32+kk)*H2D + j0);
        w2a[kk] = v.x; w2b[kk] = v.y;
    }

    // node init (independent of deps: A0/ccnt/cand are static)
    if (tid < H1D) a_[tid] = g_A0[i*H1D+tid];
    if (tid < EE)  selP[tid] = 0.f;
    if (tid == 0) {
        int c = g_ccnt[i]; s_na = c;
        for (int q = 0; q < c; q++) s_alive[q] = g_cand[i*4+q];
        s_cnt = 0.f; s_done = 0; s_gdirty = 0;
    }

    // ---- wait for all conflicting j < i (warp 0 spins) ----
    if (w == 0){
        ull myL = g_mL[i], myH = g_mH[i];
        unsigned pend = 0;
        #pragma unroll
        for (int q = 0; q < 4; q++){
            int j = lane + q*32;
            if (j < i && (((g_mL[j] & myL) | (g_mH[j] & myH)) != 0ull))
                pend |= 1u << q;
        }
        while (__ballot_sync(0xffffffffu, pend != 0u)){
            #pragma unroll
            for (int q = 0; q < 4; q++){
                if (pend & (1u << q)){
                    if (ld_acquire(&g_done[lane + q*32])) pend &= ~(1u << q);
                }
            }
        }
    }
    __syncthreads();   // deps complete; their writes (via L2, acquired) now safe

    // -------- step loop (validated R2 body + R5 early-breaks) --------
    for (int step = 0; step < 3; step++) {
        int na = s_na;
        if (na == 0) break;
        int nrows = na + 1;

        // S1: h1T[k][r] = relu(a_k + G_vr_k + b1_k)
        {
            int k = tid & 255, rp = tid >> 8;
            float ak = a_[k] + b1s[k];
            #pragma unroll
            for (int rr = 0; rr < 2; rr++){
                int r = rp*2 + rr;
                float val = 0.f;
                if (r < na) { int v = s_alive[r];
                              float g = (v > 0) ? g_G[v*H1D+k] : 0.f;   // `if v>0` quirk
                              val = fmaxf(ak + g, 0.f); }
                else if (r == na) val = fmaxf(ak, 0.f);                  // sentinel
                h1T[k*4+r] = val;
            }
        }
        __syncthreads();

        // S2: packed f32x2 row-pairs, W2 in regs
        if (nrows > 2) {
            ull a01a=0, a23a=0, a01b=0, a23b=0;
            #pragma unroll
            for (int kk = 0; kk < 32; kk++){
                int k = kslab*32 + kk;
                ulonglong2 hp = *(const ulonglong2*)(h1T + 4*k);
                ull wpa = packff(w2a[kk]), wpb = packff(w2b[kk]);
                a01a = ffma2(hp.x, wpa, a01a);
                a23a = ffma2(hp.y, wpa, a23a);
                a01b = ffma2(hp.x, wpb, a01b);
                a23b = ffma2(hp.y, wpb, a23b);
            }
            part01[kslab*H2D+j0]   = *(float2*)&a01a;
            part01[kslab*H2D+j0+1] = *(float2*)&a01b;
            part23[kslab*H2D+j0]   = *(float2*)&a23a;
            part23[kslab*H2D+j0+1] = *(float2*)&a23b;
        } else {
            ull a01a=0, a01b=0;
            #pragma unroll
            for (int kk = 0; kk < 32; kk++){
                int k = kslab*32 + kk;
                ull hx = *(const ull*)(h1T + 4*k);
                ull wpa = packff(w2a[kk]), wpb = packff(w2b[kk]);
                a01a = ffma2(hx, wpa, a01a);
                a01b = ffma2(hx, wpb, a01b);
            }
            part01[kslab*H2D+j0]   = *(float2*)&a01a;
            part01[kslab*H2D+j0+1] = *(float2*)&a01b;
        }
        __syncthreads();

        // S3: per-row lk / act dots
        if (w < nrows) {
            const float2* pr = (w < 2) ? part01 : part23;
            int hi = w & 1;
            float lk = 0.f, p0 = 0.f, p1 = 0.f;
            #pragma unroll
            for (int q = 0; q < 4; q++){
                int j = lane + q*32;
                float s = b2s[j];
                #pragma unroll
                for (int ks = 0; ks < 8; ks++){
                    float2 v = pr[ks*H2D + j];
                    s += hi ? v.y : v.x;
                }
                float h = fmaxf(s, 0.f);
                lk += h*wlks[j]; p0 += h*wa0[j]; p1 += h*wa1[j];
            }
            #pragma unroll
            for (int off = 16; off; off >>= 1){
                lk += __shfl_xor_sync(0xffffffffu, lk, off);
                p0 += __shfl_xor_sync(0xffffffffu, p0, off);
                p1 += __shfl_xor_sync(0xffffffffu, p1, off);
            }
            if (lane == 0){ s_lk[w]=lk+s_blk; s_a0[w]=p0+s_ba0; s_a1[w]=p1+s_ba1; }
        }
        __syncthreads();

        // S4a: argmax decision
        if (tid == 0) {
            float best = -3.4028235e38f; int bi = -1;
            for (int r = 0; r < na; r++)
                if (s_lk[r] > best) { best = s_lk[r]; bi = r; }
            if (s_lk[na] > best) {
                s_done = 1;
            } else {
                int v  = s_alive[bi];
                int at = (s_a1[bi] > s_a0[bi]) ? 1 : 0;
                s_vsel = v; s_at = at;
                s_denom = s_cnt + (float)at + 1.0f;
                s_cnt  += (float)at;
                for (int q = bi; q < na-1; q++) s_alive[q] = s_alive[q+1];
                s_na = na - 1;
                int ng = 0;
                for (int q = 0; q < na-1; q++) if (s_alive[q] == i) ng = 1;
                s_needgi = ng;
                s_gdirty = (v == i) ? 0 : 1;
                g_upd[i] = 1; g_upd[v] = 1;
            }
        }
        __syncthreads();
        if (s_done) break;

        // S4b: apply updates in projected space
        {
            int v = s_vsel; float atf = (float)s_at; float denom = s_denom;
            if (tid < EE) {
                int e = tid;
                float pv = g_P[v*EE+e], pi = g_P[i*EE+e];
                float nx = fmaxf((selP[e] + atf*pv + pi)/denom + bes[e], 0.f);
                if (s_at) selP[e] += pv;
                float f0v = g_feat0[v*EE+e];
                g_feat[v*EE+e] = f0v;
                float fx = (v == i) ? f0v : nx;
                g_feat[i*EE+e] = fx;
                curx[e] = fx;
            } else if (tid < EE + H1D) {
                int jj = tid - EE;
                g_G[v*H1D + jj] = g_G0[v*H1D + jj];
            }
        }
        __syncthreads();
        if (s_na == 0) break;          // no more decisions possible
        if (step >= 2) break;          // a_ dead after; flush covers G[i]

        // S5: a = curx @ W1_top (L1-resident after first step); + G[i] if needed
        {
            int jg = tid & 63, ks = tid >> 6;
            const float* base = W1 + (ks*16)*H1D + jg*4;
            float4 acc = make_float4(0.f,0.f,0.f,0.f);
            #pragma unroll
            for (int kk = 0; kk < 16; kk++){
                float4 wr = *(const float4*)(base + kk*H1D);
                float c = curx[ks*16+kk];
                acc.x += c*wr.x; acc.y += c*wr.y; acc.z += c*wr.z; acc.w += c*wr.w;
            }
            *(float4*)(dual + ks*H1D + jg*4) = acc;
            if (s_needgi) {
                float* dualB = (float*)part01;
                const float* baseB = W1 + (EE + ks*16)*H1D + jg*4;
                float4 ab = make_float4(0.f,0.f,0.f,0.f);
                #pragma unroll
                for (int kk = 0; kk < 16; kk++){
                    float4 wr = *(const float4*)(baseB + kk*H1D);
                    float c = curx[ks*16+kk];
                    ab.x += c*wr.x; ab.y += c*wr.y; ab.z += c*wr.z; ab.w += c*wr.w;
                }
                *(float4*)(dualB + ks*H1D + jg*4) = ab;
            }
        }
        __syncthreads();
        if (tid < H1D){
            float s = 0.f;
            #pragma unroll
            for (int ks = 0; ks < 8; ks++) s += dual[ks*H1D+tid];
            a_[tid] = s;
            if (s_needgi){
                const float* dualB = (const float*)part01;
                float sb = 0.f;
                #pragma unroll
                for (int ks = 0; ks < 8; ks++) sb += dualB[ks*H1D+tid];
                g_G[i*H1D+tid] = sb;
            }
        }
        if (tid == 0 && s_needgi) s_gdirty = 0;
        __syncthreads();
    } // steps

    // node end: lazy G[i] = feature[i] @ W1_bot (only if stale)
    if (s_gdirty) {
        {
            int jg = tid & 63, ks = tid >> 6;
            const float* baseB = W1 + (EE + ks*16)*H1D + jg*4;
            float4 acc = make_float4(0.f,0.f,0.f,0.f);
            #pragma unroll
            for (int kk = 0; kk < 16; kk++){
                float4 wr = *(const float4*)(baseB + kk*H1D);
                float c = curx[ks*16+kk];
                acc.x += c*wr.x; acc.y += c*wr.y; acc.z += c*wr.z; acc.w += c*wr.w;
            }
            *(float4*)(dual + ks*H1D + jg*4) = acc;
        }
        __syncthreads();
        if (tid < H1D){
            float s = 0.f;
            #pragma unroll
            for (int ks = 0; ks < 8; ks++) s += dual[ks*H1D+tid];
            g_G[i*H1D+tid] = s;
        }
    }

    // ---- publish: all writes visible, then release done flag ----
    __threadfence();
    __syncthreads();
    if (tid == 0) st_release(&g_done[i], 1);
}

// ---------------- output: zero untouched rows --------------------------------
__global__ void out_kernel(float* __restrict__ out)
{
    int t = blockIdx.x*blockDim.x + threadIdx.x;
    if (t < NN*EE) out[t] = g_upd[t >> 7] ? g_feat[t] : 0.f;
}

// ---------------- launch ------------------------------------------------------
extern "C" void kernel_launch(void* const* d_in, const int* in_sizes, int n_in,
                              void* d_out, int out_size)
{
    const float* adj = (const float*)d_in[0];
    const float* fo  = (const float*)d_in[1];
    // d_in[2] = labels (unused)
    const float* We  = (const float*)d_in[3];
    const float* be  = (const float*)d_in[4];
    const float* W1  = (const float*)d_in[5];
    const float* b1  = (const float*)d_in[6];
    const float* W2  = (const float*)d_in[7];
    const float* b2  = (const float*)d_in[8];
    const float* wlk = (const float*)d_in[9];
    const float* blk = (const float*)d_in[10];
    const float* wac = (const float*)d_in[11];
    const float* bac = (const float*)d_in[12];
    float* out = (float*)d_out;

    initA_kernel<<<32, 512>>>(fo, We, be, adj);
    initB_kernel<<<NN, H1D>>>(W1);
    dataflow_kernel<<<NN, TPB>>>(W1, W2, b1, b2, wlk, blk, wac, bac, be);
    out_kernel<<<32, 512>>>(out);
}

// round 8
// speedup vs baseline: 5.5215x; 1.1427x over previous
#include <cuda_runtime.h>

#define NN   128
#define FIN  512
#define EE   128
#define H1D  256
#define H2D  128
#define TPB  512

typedef unsigned long long ull;

__device__ __forceinline__ ull ffma2(ull a, ull b, ull c){
    ull d;
    asm("fma.rn.f32x2 %0, %1, %2, %3;" : "=l"(d) : "l"(a), "l"(b), "l"(c));
    return d;
}
__device__ __forceinline__ ull packff(float x){
    ull d; asm("mov.b64 %0, {%1, %2};" : "=l"(d) : "f"(x), "f"(x)); return d;
}
__device__ __forceinline__ int ld_acquire(const int* p){
    int v;
    asm volatile("ld.acquire.gpu.global.b32 %0, [%1];" : "=r"(v) : "l"(p) : "memory");
    return v;
}
__device__ __forceinline__ void st_release(int* p, int v){
    asm volatile("st.release.gpu.global.b32 [%0], %1;" :: "l"(p), "r"(v) : "memory");
}

// ---------------- persistent device state ----------------------------------
__device__ float g_P[NN*EE];
__device__ float g_feat0[NN*EE];
__device__ float g_A0[NN*H1D];
__device__ float g_G0[NN*H1D];
__device__ float g_G[NN*H1D];
__device__ float g_feat[NN*EE];
__device__ int   g_cand[NN*4];
__device__ int   g_ccnt[NN];
__device__ int   g_upd[NN];
__device__ ull   g_mL[NN], g_mH[NN];
__device__ int   g_done[NN];
__device__ int   g_needany[NN];

// ---------------- initA: 4 nodes per block ----------------------------------
__global__ void initA_kernel(const float* __restrict__ fo, const float* __restrict__ We,
                             const float* __restrict__ be, const float* __restrict__ adj)
{
    __shared__ float fos[4][FIN];
    __shared__ unsigned bal[4][4];
    int m = threadIdx.x >> 7;
    int e = threadIdx.x & 127;
    int i = blockIdx.x*4 + m;
    ((float4*)fos[m])[e] = ((const float4*)(fo + i*FIN))[e];
    unsigned b = __ballot_sync(0xffffffffu, adj[i*NN + e] != 0.0f);
    if ((e & 31) == 0) bal[m][e >> 5] = b;
    __syncthreads();

    float s = 0.f;
    #pragma unroll 16
    for (int f = 0; f < FIN; f++) s += fos[m][f] * We[f*EE + e];
    g_P[i*EE+e] = s;
    float f0 = fmaxf(s + be[e], 0.f);
    g_feat0[i*EE+e] = f0;
    g_feat [i*EE+e] = f0;

    if (e == 0) {
        g_upd[i]  = 0;
        g_done[i] = 0;
        int c = 0; ull ml = 0, mh = 0;
        if (i < 64) ml |= 1ull << i; else mh |= 1ull << (i-64);
        for (int wq = 0; wq < 4; wq++){
            unsigned bb = bal[m][wq];
            while (bb){
                int bit = __ffs(bb) - 1; bb &= bb - 1;
                int vtx = wq*32 + bit;
                if (c < 4) g_cand[i*4 + c] = vtx;
                c++;
                if (vtx < 64) ml |= 1ull << vtx; else mh |= 1ull << (vtx-64);
            }
        }
        if (c > 3) c = 3;                              // K=3 -> <=3 distinct
        g_ccnt[i] = c;
        g_mL[i] = ml; g_mH[i] = mh;
    }
}

// ---------------- initB: A0/G0/G + needany ----------------------------------
__global__ void initB_kernel(const float* __restrict__ W1, const float* __restrict__ adj)
{
    __shared__ float fs[EE];
    int i = blockIdx.x, j = threadIdx.x;               // 256 threads
    if (j < EE) fs[j] = g_feat0[i*EE + j];
    int fl = (j < NN && j > i) ? (adj[j*NN + i] != 0.0f) : 0;
    int any = __syncthreads_or(fl);
    if (j == 0) g_needany[i] = any;

    float st = 0.f, sb = 0.f;
    #pragma unroll 16
    for (int k = 0; k < EE; k++){
        float f = fs[k];
        st += f * W1[k*H1D + j];
        sb += f * W1[(EE+k)*H1D + j];
    }
    g_A0[i*H1D+j] = st;
    g_G0[i*H1D+j] = sb;
    g_G [i*H1D+j] = sb;
}

// ---------------- S2: NPAIR row-pairs, W2 from smem --------------------------
template<int NPAIR>
__device__ __forceinline__ void s2_compute(const float* __restrict__ h1T,
                                           const float* __restrict__ W2s,
                                           float2* __restrict__ part,
                                           int kslab, int j0)
{
    ull accA[NPAIR], accB[NPAIR];
    #pragma unroll
    for (int p = 0; p < NPAIR; p++){ accA[p] = 0ull; accB[p] = 0ull; }
    #pragma unroll
    for (int kk = 0; kk < 32; kk++){
        int k = kslab*32 + kk;
        float2 wv = *(const float2*)(W2s + k*H2D + j0);
        ull wpa = packff(wv.x), wpb = packff(wv.y);
        if (NPAIR == 2){
            ulonglong2 hp = *(const ulonglong2*)(h1T + 4*k);
            accA[0] = ffma2(hp.x, wpa, accA[0]);
            accB[0] = ffma2(hp.x, wpb, accB[0]);
            accA[1] = ffma2(hp.y, wpa, accA[1]);
            accB[1] = ffma2(hp.y, wpb, accB[1]);
        } else {
            ull hx = *(const ull*)(h1T + 4*k);
            accA[0] = ffma2(hx, wpa, accA[0]);
            accB[0] = ffma2(hx, wpb, accB[0]);
        }
    }
    #pragma unroll
    for (int p = 0; p < NPAIR; p++){
        float2 fa, fb;
        asm("mov.b64 {%0,%1}, %2;" : "=f"(fa.x), "=f"(fa.y) : "l"(accA[p]));
        asm("mov.b64 {%0,%1}, %2;" : "=f"(fb.x), "=f"(fb.y) : "l"(accB[p]));
        part[(p*8 + kslab)*H2D + j0]     = fa;
        part[(p*8 + kslab)*H2D + j0 + 1] = fb;
    }
}

// ---------------- dataflow rollout: 128 CTAs, one node each ------------------
extern __shared__ float smx[];

__global__ void __launch_bounds__(TPB, 1) dataflow_kernel(
    const float* __restrict__ W1, const float* __restrict__ W2,
    const float* __restrict__ b1, const float* __restrict__ b2,
    const float* __restrict__ wlk, const float* __restrict__ blk,
    const float* __restrict__ wact, const float* __restrict__ bact,
    const float* __restrict__ be, float* __restrict__ out)
{
    float* base_ = smx;
    float*  W2s  = base_;  base_ += 32768;   // W2 [256k][128j]
    float*  h1T  = base_;  base_ += 1024;    // [k][4 slots]
    float*  partF= base_;  base_ += 4096;    // S2 partials; aliased by dual/dualB
    float*  Grow = base_;  base_ += 768;     // candidate G rows [3][256]
    float*  G0s  = base_;  base_ += 768;     // candidate G0 rows
    float*  Pvs  = base_;  base_ += 384;     // candidate P rows [3][128]
    float*  f0vs = base_;  base_ += 384;     // candidate feat0 rows
    float*  Pis  = base_;  base_ += 128;
    float*  a_   = base_;  base_ += 256;
    float*  curx = base_;  base_ += 128;
    float*  selP = base_;  base_ += 128;
    float*  b1s  = base_;  base_ += 256;
    float*  b2s  = base_;  base_ += 128;
    float*  wlks = base_;  base_ += 128;
    float*  wa0  = base_;  base_ += 128;
    float*  wa1  = base_;  base_ += 128;
    float*  bes  = base_;  base_ += 128;

    float2* part  = (float2*)partF;
    float*  dual  = partF;            // 2048 floats
    float*  dualB = partF + 2048;     // 2048 floats

    __shared__ float s_lk[4], s_a0[4], s_a1[4];

    const int i    = blockIdx.x;
    const int tid  = threadIdx.x;
    const int w    = tid >> 5;
    const int lane = tid & 31;
    const int kslab = w >> 1, jh = w & 1;
    const int j0 = jh*64 + lane*2;
    const int jg = tid & 63, ks = tid >> 6;

    // ---- pre-wait: constants, W2->smem, W1_top->regs, static prefetch ----
    if (tid < H1D) b1s[tid] = b1[tid];
    if (tid < H2D){ b2s[tid]=b2[tid]; wlks[tid]=wlk[tid];
                    wa0[tid]=wact[2*tid]; wa1[tid]=wact[2*tid+1]; }
    if (tid < EE){ bes[tid] = be[tid]; selP[tid] = 0.f; Pis[tid] = g_P[i*EE+tid]; }
    if (tid < H1D) a_[tid] = g_A0[i*H1D + tid];
    const float blkv = __ldg(blk), ba0v = __ldg(bact), ba1v = __ldg(bact+1);

    #pragma unroll
    for (int q = 0; q < 16; q++)
        ((float4*)W2s)[q*TPB + tid] = ((const float4*)W2)[q*TPB + tid];

    float4 w1r[16];
    #pragma unroll
    for (int kk = 0; kk < 16; kk++)
        w1r[kk] = *(const float4*)(W1 + (ks*16+kk)*H1D + jg*4);

    const int cc = g_ccnt[i];
    int candv[3];
    #pragma unroll
    for (int q = 0; q < 3; q++) candv[q] = (q < cc) ? g_cand[i*4+q] : 0;
    const int needany = g_needany[i];

    for (int t = tid; t < 768; t += TPB){
        int q = t >> 8, k = t & 255;
        if (q < cc) G0s[q*256+k] = g_G0[candv[q]*H1D + k];
    }
    if (tid < 384){
        int q = tid >> 7, e = tid & 127;
        if (q < cc){ Pvs[q*128+e] = g_P[candv[q]*EE+e];
                     f0vs[q*128+e] = g_feat0[candv[q]*EE+e]; }
    }

    // ---- wait for all conflicting j < i (warp 0 spins) ----
    ull myL = 0, myH = 0;
    if (w == 0){
        myL = g_mL[i]; myH = g_mH[i];
        unsigned pend = 0;
        #pragma unroll
        for (int q = 0; q < 4; q++){
            int j = lane + q*32;
            if (j < i && (((g_mL[j] & myL) | (g_mH[j] & myH)) != 0ull))
                pend |= 1u << q;
        }
        while (__ballot_sync(0xffffffffu, pend != 0u)){
            #pragma unroll
            for (int q = 0; q < 4; q++){
                if (pend & (1u << q)){
                    if (ld_acquire(&g_done[lane + q*32])) pend &= ~(1u << q);
                }
            }
        }
    }
    __syncthreads();   // deps done + smem staging complete

    // ---- per-thread uniform rollout state ----
    int aliveM = (1 << cc) - 1, na = cc;
    int done = 0, gdirty = 0, needgi = 0, qi = -1;
    float cntf = 0.f;

    for (int step = 0; step < 3; step++){
        if (na == 0) break;

        int slots[4]; int ns = 0;
        #pragma unroll
        for (int q = 0; q < 3; q++) if ((aliveM >> q) & 1) slots[ns++] = q;
        slots[ns++] = -1;                       // sentinel last
        int npair = (ns + 1) >> 1;

        // S1: h1T[k][slot]
        {
            int k = tid & 255, hi = tid >> 8;
            float ak = a_[k] + b1s[k];
            #pragma unroll
            for (int h = 0; h < 2; h++){
                int s = hi*2 + h; float val = 0.f;
                if (s < ns){
                    int q = slots[s];
                    if (q < 0) val = fmaxf(ak, 0.f);
                    else {
                        int v = candv[q]; float gg;
                        if (step == 0){
                            gg = (v > 0) ? g_G[v*H1D + k] : 0.f;   // `if v>0` quirk
                            Grow[q*256 + k] = gg;
                        } else gg = (v > 0) ? Grow[q*256 + k] : 0.f;
                        val = fmaxf(ak + gg, 0.f);
                    }
                }
                h1T[k*4 + s] = val;
            }
        }
        __syncthreads();

        // S2
        if (npair == 2) s2_compute<2>(h1T, W2s, part, kslab, j0);
        else            s2_compute<1>(h1T, W2s, part, kslab, j0);
        __syncthreads();

        // S3: warp per slot
        if (w < ns){
            int pair = w >> 1, el = w & 1;
            float lk = 0.f, p0 = 0.f, p1 = 0.f;
            #pragma unroll
            for (int qq = 0; qq < 4; qq++){
                int j = lane + qq*32;
                float ssm = b2s[j];
                #pragma unroll
                for (int kq = 0; kq < 8; kq++){
                    float2 vv = part[(pair*8 + kq)*H2D + j];
                    ssm += el ? vv.y : vv.x;
                }
                float h = fmaxf(ssm, 0.f);
                lk += h*wlks[j]; p0 += h*wa0[j]; p1 += h*wa1[j];
            }
            #pragma unroll
            for (int off = 16; off; off >>= 1){
                lk += __shfl_xor_sync(0xffffffffu, lk, off);
                p0 += __shfl_xor_sync(0xffffffffu, p0, off);
                p1 += __shfl_xor_sync(0xffffffffu, p1, off);
            }
            if (lane == 0){ s_lk[w]=lk+blkv; s_a0[w]=p0+ba0v; s_a1[w]=p1+ba1v; }
        }
        __syncthreads();

        // Decision — all threads, uniform registers
        float best = -3.4028235e38f; int bs = -1;
        for (int s = 0; s < ns-1; s++){
            float l = s_lk[s];
            if (l > best){ best = l; bs = s; }
        }
        int vsel = 0, at = 0, qsel = -1; float denom = 1.f;
        if (s_lk[ns-1] > best){
            done = 1;
        } else {
            #pragma unroll
            for (int s = 0; s < 3; s++) if (s == bs) qsel = slots[s];
            vsel = candv[qsel];
            at = (s_a1[bs] > s_a0[bs]) ? 1 : 0;
            denom = cntf + (float)at + 1.0f;
            cntf += (float)at;
            aliveM &= ~(1 << qsel); na--;
            needgi = 0; qi = -1;
            #pragma unroll
            for (int q = 0; q < 3; q++)
                if (((aliveM >> q) & 1) && candv[q] == i){ needgi = 1; qi = q; }
            gdirty = (vsel == i) ? 0 : 1;
        }
        if (done) break;

        // S4b: apply updates (all-smem sources)
        {
            if (tid == 0){ g_upd[i] = 1; g_upd[vsel] = 1; }
            int grp = tid >> 7, e = tid & 127;
            if (grp == 0){
                float pv = Pvs[qsel*128+e], pi = Pis[e];
                float nx = fmaxf((selP[e] + (float)at*pv + pi)/denom + bes[e], 0.f);
                float f0v = f0vs[qsel*128+e];
                float fx = (vsel == i) ? f0v : nx;
                if (at) selP[e] += pv;
                g_feat[i*EE + e] = fx;
                curx[e] = fx;
            } else if (grp == 1){
                g_feat[vsel*EE + e] = f0vs[qsel*128+e];
            } else {
                int jj = tid - 256;
                g_G[vsel*H1D + jj] = G0s[qsel*256 + jj];
            }
        }
        __syncthreads();
        if (na == 0) break;
        if (step >= 2) break;

        // S5: a = curx @ W1_top (registers); + G[i] bottom LDG stream if needgi
        {
            float4 acc = make_float4(0.f,0.f,0.f,0.f);
            #pragma unroll
            for (int kk = 0; kk < 16; kk++){
                float c = curx[ks*16 + kk];
                acc.x += c*w1r[kk].x; acc.y += c*w1r[kk].y;
                acc.z += c*w1r[kk].z; acc.w += c*w1r[kk].w;
            }
            float4 ab = make_float4(0.f,0.f,0.f,0.f);
            if (needgi){
                const float* bwB = W1 + (EE + ks*16)*H1D + jg*4;
                #pragma unroll
                for (int kk = 0; kk < 16; kk++){
                    float4 wr = *(const float4*)(bwB + kk*H1D);
                    float c = curx[ks*16 + kk];
                    ab.x += c*wr.x; ab.y += c*wr.y; ab.z += c*wr.z; ab.w += c*wr.w;
                }
            }
            *(float4*)(dual + ks*H1D + jg*4) = acc;     // partF dead here
            if (needgi) *(float4*)(dualB + ks*H1D + jg*4) = ab;
        }
        __syncthreads();
        if (tid < H1D){
            float ssum = 0.f;
            #pragma unroll
            for (int kq = 0; kq < 8; kq++) ssum += dual[kq*H1D + tid];
            a_[tid] = ssum;
        } else if (needgi){
            int jj = tid - 256;
            float sb = 0.f;
            #pragma unroll
            for (int kq = 0; kq < 8; kq++) sb += dualB[kq*H1D + jj];
            g_G[i*H1D + jj] = sb;
            Grow[qi*256 + jj] = sb;
        }
        if (needgi) gdirty = 0;
        __syncthreads();
    } // steps

    // ---- flush stale G[i] only if some j>i can read it ----
    if (gdirty && needany){
        {
            const float* bwB = W1 + (EE + ks*16)*H1D + jg*4;
            float4 acc = make_float4(0.f,0.f,0.f,0.f);
            #pragma unroll
            for (int kk = 0; kk < 16; kk++){
                float4 wr = *(const float4*)(bwB + kk*H1D);
                float c = curx[ks*16 + kk];
                acc.x += c*wr.x; acc.y += c*wr.y; acc.z += c*wr.z; acc.w += c*wr.w;
            }
            *(float4*)(dual + ks*H1D + jg*4) = acc;
        }
        __syncthreads();
        if (tid < H1D){
            float ssum = 0.f;
            #pragma unroll
            for (int kq = 0; kq < 8; kq++) ssum += dual[kq*H1D + tid];
            g_G[i*H1D + tid] = ssum;
        }
    }

    // ---- publish ----
    __threadfence();
    __syncthreads();
    if (tid == 0) st_release(&g_done[i], 1);

    // ---- out phase: wait conflicting j > i, then write own row ----
    if (w == 0){
        unsigned pend = 0;
        #pragma unroll
        for (int q = 0; q < 4; q++){
            int j = lane + q*32;
            if (j > i && (((g_mL[j] & myL) | (g_mH[j] & myH)) != 0ull))
                pend |= 1u << q;
        }
        while (__ballot_sync(0xffffffffu, pend != 0u)){
            #pragma unroll
            for (int q = 0; q < 4; q++){
                if (pend & (1u << q)){
                    if (ld_acquire(&g_done[lane + q*32])) pend &= ~(1u << q);
                }
            }
        }
    }
    __syncthreads();
    if (tid < EE){
        int u  = __ldcg(&g_upd[i]);
        float f = __ldcg(&g_feat[i*EE + tid]);
        out[i*EE + tid] = u ? f : 0.f;
    }
}

// ---------------- launch ------------------------------------------------------
static const int DYN_SMEM = (32768 + 1024 + 4096 + 768 + 768 + 384 + 384
                             + 128 + 256 + 128 + 128 + 256 + 128 + 128
                             + 128 + 128 + 128) * (int)sizeof(float);

extern "C" void kernel_launch(void* const* d_in, const int* in_sizes, int n_in,
                              void* d_out, int out_size)
{
    const float* adj = (const float*)d_in[0];
    const float* fo  = (const float*)d_in[1];
    // d_in[2] = labels (unused)
    const float* We  = (const float*)d_in[3];
    const float* be  = (const float*)d_in[4];
    const float* W1  = (const float*)d_in[5];
    const float* b1  = (const float*)d_in[6];
    const float* W2  = (const float*)d_in[7];
    const float* b2  = (const float*)d_in[8];
    const float* wlk = (const float*)d_in[9];
    const float* blk = (const float*)d_in[10];
    const float* wac = (const float*)d_in[11];
    const float* bac = (const float*)d_in[12];
    float* out = (float*)d_out;

    cudaFuncSetAttribute(dataflow_kernel, cudaFuncAttributeMaxDynamicSharedMemorySize, DYN_SMEM);

    initA_kernel<<<32, 512>>>(fo, We, be, adj);
    initB_kernel<<<NN, H1D>>>(W1, adj);
    dataflow_kernel<<<NN, TPB, DYN_SMEM>>>(W1, W2, b1, b2, wlk, blk, wac, bac, be, out);
}

// round 9
// speedup vs baseline: 5.7599x; 1.0432x over previous
#include <cuda_runtime.h>

#define NN   128
#define FIN  512
#define EE   128
#define H1D  256
#define H2D  128
#define TPB  512

typedef unsigned long long ull;

__device__ __forceinline__ ull ffma2(ull a, ull b, ull c){
    ull d;
    asm("fma.rn.f32x2 %0, %1, %2, %3;" : "=l"(d) : "l"(a), "l"(b), "l"(c));
    return d;
}
__device__ __forceinline__ ull packff(float x){
    ull d; asm("mov.b64 %0, {%1, %2};" : "=l"(d) : "f"(x), "f"(x)); return d;
}
__device__ __forceinline__ int ld_acquire(const int* p){
    int v;
    asm volatile("ld.acquire.gpu.global.b32 %0, [%1];" : "=r"(v) : "l"(p) : "memory");
    return v;
}
__device__ __forceinline__ void st_release(int* p, int v){
    asm volatile("st.release.gpu.global.b32 [%0], %1;" :: "l"(p), "r"(v) : "memory");
}

// ---------------- persistent device state ----------------------------------
__device__ float g_P[NN*EE];
__device__ float g_feat0[NN*EE];
__device__ float g_A0[NN*H1D];
__device__ float g_G0[NN*H1D];
__device__ float g_G[NN*H1D];
__device__ float g_feat[NN*EE];
__device__ int   g_cand[NN*4];
__device__ int   g_ccnt[NN];
__device__ int   g_upd[NN];
__device__ ull   g_mL[NN], g_mH[NN];
__device__ int   g_done[NN];    // S4b writes (feat/upd/G[vsel]) visible
__device__ int   g_doneG[NN];   // + final G[i] flush visible
__device__ int   g_needany[NN];

// ---------------- fused init: one node per block (128 thr) ------------------
__global__ void init_kernel(const float* __restrict__ fo, const float* __restrict__ We,
                            const float* __restrict__ be, const float* __restrict__ adj,
                            const float* __restrict__ W1)
{
    __shared__ float fos[FIN];
    __shared__ float fs[EE];
    __shared__ unsigned bal[4];
    const int i = blockIdx.x, e = threadIdx.x;     // 128 threads

    ((float4*)fos)[e] = ((const float4*)(fo + i*FIN))[e];
    unsigned b = __ballot_sync(0xffffffffu, adj[i*NN + e] != 0.0f);
    if ((e & 31) == 0) bal[e >> 5] = b;
    int fl = (e > i) ? (adj[e*NN + i] != 0.0f) : 0;
    int any = __syncthreads_or(fl);
    if (e == 0) g_needany[i] = any;

    // P / feat0 (exact per-output f order)
    float s = 0.f;
    #pragma unroll 16
    for (int f = 0; f < FIN; f++) s += fos[f] * We[f*EE + e];
    g_P[i*EE+e] = s;
    float f0 = fmaxf(s + be[e], 0.f);
    g_feat0[i*EE+e] = f0;
    g_feat [i*EE+e] = f0;
    fs[e] = f0;

    if (e == 0) {
        g_upd[i]   = 0;
        g_done[i]  = 0;
        g_doneG[i] = 0;
        int c = 0; ull ml = 0, mh = 0;
        if (i < 64) ml |= 1ull << i; else mh |= 1ull << (i-64);
        for (int wq = 0; wq < 4; wq++){
            unsigned bb = bal[wq];
            while (bb){
                int bit = __ffs(bb) - 1; bb &= bb - 1;
                int vtx = wq*32 + bit;
                if (c < 4) g_cand[i*4 + c] = vtx;
                c++;
                if (vtx < 64) ml |= 1ull << vtx; else mh |= 1ull << (vtx-64);
            }
        }
        if (c > 3) c = 3;                          // K=3 -> <=3 distinct
        g_ccnt[i] = c;
        g_mL[i] = ml; g_mH[i] = mh;
    }
    __syncthreads();

    // A0 / G0 / G (exact per-output k order; 2 j-outputs per thread)
    #pragma unroll
    for (int h = 0; h < 2; h++){
        int j = e + h*128;
        float st = 0.f, sb = 0.f;
        #pragma unroll 16
        for (int k = 0; k < EE; k++){
            float f = fs[k];
            st += f * W1[k*H1D + j];
            sb += f * W1[(EE+k)*H1D + j];
        }
        g_A0[i*H1D+j] = st;
        g_G0[i*H1D+j] = sb;
        g_G [i*H1D+j] = sb;
    }
}

// ---------------- S2: NPAIR row-pairs, W2 from smem --------------------------
template<int NPAIR>
__device__ __forceinline__ void s2_compute(const float* __restrict__ h1T,
                                           const float* __restrict__ W2s,
                                           float2* __restrict__ part,
                                           int kslab, int j0)
{
    ull accA[NPAIR], accB[NPAIR];
    #pragma unroll
    for (int p = 0; p < NPAIR; p++){ accA[p] = 0ull; accB[p] = 0ull; }
    #pragma unroll
    for (int kk = 0; kk < 32; kk++){
        int k = kslab*32 + kk;
        float2 wv = *(const float2*)(W2s + k*H2D + j0);
        ull wpa = packff(wv.x), wpb = packff(wv.y);
        if (NPAIR == 2){
            ulonglong2 hp = *(const ulonglong2*)(h1T + 4*k);
            accA[0] = ffma2(hp.x, wpa, accA[0]);
            accB[0] = ffma2(hp.x, wpb, accB[0]);
            accA[1] = ffma2(hp.y, wpa, accA[1]);
            accB[1] = ffma2(hp.y, wpb, accB[1]);
        } else {
            ull hx = *(const ull*)(h1T + 4*k);
            accA[0] = ffma2(hx, wpa, accA[0]);
            accB[0] = ffma2(hx, wpb, accB[0]);
        }
    }
    #pragma unroll
    for (int p = 0; p < NPAIR; p++){
        float2 fa, fb;
        asm("mov.b64 {%0,%1}, %2;" : "=f"(fa.x), "=f"(fa.y) : "l"(accA[p]));
        asm("mov.b64 {%0,%1}, %2;" : "=f"(fb.x), "=f"(fb.y) : "l"(accB[p]));
        part[(p*8 + kslab)*H2D + j0]     = fa;
        part[(p*8 + kslab)*H2D + j0 + 1] = fb;
    }
}

// ---------------- dataflow rollout: 128 CTAs, one node each ------------------
extern __shared__ float smx[];

__global__ void __launch_bounds__(TPB, 1) dataflow_kernel(
    const float* __restrict__ W1, const float* __restrict__ W2,
    const float* __restrict__ b1, const float* __restrict__ b2,
    const float* __restrict__ wlk, const float* __restrict__ blk,
    const float* __restrict__ wact, const float* __restrict__ bact,
    const float* __restrict__ be, float* __restrict__ out)
{
    float* base_ = smx;
    float*  W2s  = base_;  base_ += 32768;   // W2 [256k][128j]
    float*  h1T  = base_;  base_ += 1024;    // [k][4 slots]
    float*  partF= base_;  base_ += 4096;    // S2 partials; aliased by dual/dualB
    float*  Grow = base_;  base_ += 768;     // candidate G rows [3][256]
    float*  G0s  = base_;  base_ += 768;     // candidate G0 rows
    float*  Pvs  = base_;  base_ += 384;     // candidate P rows [3][128]
    float*  f0vs = base_;  base_ += 384;     // candidate feat0 rows
    float*  Pis  = base_;  base_ += 128;
    float*  a_   = base_;  base_ += 256;
    float*  curx = base_;  base_ += 128;
    float*  selP = base_;  base_ += 128;
    float*  b1s  = base_;  base_ += 256;
    float*  b2s  = base_;  base_ += 128;
    float*  wlks = base_;  base_ += 128;
    float*  wa0  = base_;  base_ += 128;
    float*  wa1  = base_;  base_ += 128;
    float*  bes  = base_;  base_ += 128;

    float2* part  = (float2*)partF;
    float*  dual  = partF;            // 2048 floats
    float*  dualB = partF + 2048;     // 2048 floats

    __shared__ float s_lk[4], s_a0[4], s_a1[4];

    const int i    = blockIdx.x;
    const int tid  = threadIdx.x;
    const int w    = tid >> 5;
    const int lane = tid & 31;
    const int kslab = w >> 1, jh = w & 1;
    const int j0 = jh*64 + lane*2;
    const int jg = tid & 63, ks = tid >> 6;

    // ---- pre-wait: constants, W2->smem, W1_top->regs, static prefetch ----
    if (tid < H1D) b1s[tid] = b1[tid];
    if (tid < H2D){ b2s[tid]=b2[tid]; wlks[tid]=wlk[tid];
                    wa0[tid]=wact[2*tid]; wa1[tid]=wact[2*tid+1]; }
    if (tid < EE){ bes[tid] = be[tid]; selP[tid] = 0.f; Pis[tid] = g_P[i*EE+tid]; }
    if (tid < H1D) a_[tid] = g_A0[i*H1D + tid];
    const float blkv = __ldg(blk), ba0v = __ldg(bact), ba1v = __ldg(bact+1);

    #pragma unroll
    for (int q = 0; q < 16; q++)
        ((float4*)W2s)[q*TPB + tid] = ((const float4*)W2)[q*TPB + tid];

    float4 w1r[16];
    #pragma unroll
    for (int kk = 0; kk < 16; kk++)
        w1r[kk] = *(const float4*)(W1 + (ks*16+kk)*H1D + jg*4);

    const int cc = g_ccnt[i];
    int candv[3];
    #pragma unroll
    for (int q = 0; q < 3; q++) candv[q] = (q < cc) ? g_cand[i*4+q] : -1;
    const int needany = g_needany[i];

    for (int t = tid; t < 768; t += TPB){
        int q = t >> 8, k = t & 255;
        if (q < cc) G0s[q*256+k] = g_G0[candv[q]*H1D + k];
    }
    if (tid < 384){
        int q = tid >> 7, e = tid & 127;
        if (q < cc){ Pvs[q*128+e] = g_P[candv[q]*EE+e];
                     f0vs[q*128+e] = g_feat0[candv[q]*EE+e]; }
    }

    // ---- wait for conflicting j < i; candidate preds need the G-flush ----
    ull myL = 0, myH = 0;
    if (w == 0){
        myL = g_mL[i]; myH = g_mH[i];
        unsigned pend = 0, candP = 0;
        #pragma unroll
        for (int q = 0; q < 4; q++){
            int j = lane + q*32;
            if (j < i && (((g_mL[j] & myL) | (g_mH[j] & myH)) != 0ull)){
                pend |= 1u << q;
                if (j == candv[0] || j == candv[1] || j == candv[2])
                    candP |= 1u << q;
            }
        }
        while (__ballot_sync(0xffffffffu, pend != 0u)){
            #pragma unroll
            for (int q = 0; q < 4; q++){
                if (pend & (1u << q)){
                    int j = lane + q*32;
                    const int* flag = (candP & (1u << q)) ? &g_doneG[j] : &g_done[j];
                    if (ld_acquire(flag)) pend &= ~(1u << q);
                }
            }
        }
    }
    __syncthreads();   // deps done + smem staging complete

    // ---- per-thread uniform rollout state ----
    int aliveM = (1 << cc) - 1, na = cc;
    int done = 0, gdirty = 0, needgi = 0, qi = -1;
    float cntf = 0.f;

    for (int step = 0; step < 3; step++){
        if (na == 0) break;

        int slots[4]; int ns = 0;
        #pragma unroll
        for (int q = 0; q < 3; q++) if ((aliveM >> q) & 1) slots[ns++] = q;
        slots[ns++] = -1;                       // sentinel last
        int npair = (ns + 1) >> 1;

        // S1: h1T[k][slot]
        {
            int k = tid & 255, hi = tid >> 8;
            float ak = a_[k] + b1s[k];
            #pragma unroll
            for (int h = 0; h < 2; h++){
                int s = hi*2 + h; float val = 0.f;
                if (s < ns){
                    int q = slots[s];
                    if (q < 0) val = fmaxf(ak, 0.f);
                    else {
                        int v = candv[q]; float gg;
                        if (step == 0){
                            gg = (v > 0) ? g_G[v*H1D + k] : 0.f;   // `if v>0` quirk
                            Grow[q*256 + k] = gg;
                        } else gg = (v > 0) ? Grow[q*256 + k] : 0.f;
                        val = fmaxf(ak + gg, 0.f);
                    }
                }
                h1T[k*4 + s] = val;
            }
        }
        __syncthreads();

        // S2
        if (npair == 2) s2_compute<2>(h1T, W2s, part, kslab, j0);
        else            s2_compute<1>(h1T, W2s, part, kslab, j0);
        __syncthreads();

        // S3: warp per slot
        if (w < ns){
            int pair = w >> 1, el = w & 1;
            float lk = 0.f, p0 = 0.f, p1 = 0.f;
            #pragma unroll
            for (int qq = 0; qq < 4; qq++){
                int j = lane + qq*32;
                float ssm = b2s[j];
                #pragma unroll
                for (int kq = 0; kq < 8; kq++){
                    float2 vv = part[(pair*8 + kq)*H2D + j];
                    ssm += el ? vv.y : vv.x;
                }
                float h = fmaxf(ssm, 0.f);
                lk += h*wlks[j]; p0 += h*wa0[j]; p1 += h*wa1[j];
            }
            #pragma unroll
            for (int off = 16; off; off >>= 1){
                lk += __shfl_xor_sync(0xffffffffu, lk, off);
                p0 += __shfl_xor_sync(0xffffffffu, p0, off);
                p1 += __shfl_xor_sync(0xffffffffu, p1, off);
            }
            if (lane == 0){ s_lk[w]=lk+blkv; s_a0[w]=p0+ba0v; s_a1[w]=p1+ba1v; }
        }
        __syncthreads();

        // Decision — all threads, uniform registers
        float best = -3.4028235e38f; int bs = -1;
        for (int s = 0; s < ns-1; s++){
            float l = s_lk[s];
            if (l > best){ best = l; bs = s; }
        }
        int vsel = 0, at = 0, qsel = -1; float denom = 1.f;
        if (s_lk[ns-1] > best){
            done = 1;
        } else {
            #pragma unroll
            for (int s = 0; s < 3; s++) if (s == bs) qsel = slots[s];
            vsel = candv[qsel];
            at = (s_a1[bs] > s_a0[bs]) ? 1 : 0;
            denom = cntf + (float)at + 1.0f;
            cntf += (float)at;
            aliveM &= ~(1 << qsel); na--;
            needgi = 0; qi = -1;
            #pragma unroll
            for (int q = 0; q < 3; q++)
                if (((aliveM >> q) & 1) && candv[q] == i){ needgi = 1; qi = q; }
            gdirty = (vsel == i) ? 0 : 1;
        }
        if (done) break;

        // S4b: apply updates (all-smem sources)
        {
            if (tid == 0){ g_upd[i] = 1; g_upd[vsel] = 1; }
            int grp = tid >> 7, e = tid & 127;
            if (grp == 0){
                float pv = Pvs[qsel*128+e], pi = Pis[e];
                float nx = fmaxf((selP[e] + (float)at*pv + pi)/denom + bes[e], 0.f);
                float f0v = f0vs[qsel*128+e];
                float fx = (vsel == i) ? f0v : nx;
                if (at) selP[e] += pv;
                g_feat[i*EE + e] = fx;
                curx[e] = fx;
            } else if (grp == 1){
                g_feat[vsel*EE + e] = f0vs[qsel*128+e];
            } else {
                int jj = tid - 256;
                g_G[vsel*H1D + jj] = G0s[qsel*256 + jj];
            }
        }
        __syncthreads();
        if (na == 0) break;
        if (step >= 2) break;

        // S5: a = curx @ W1_top (registers); + G[i] bottom LDG stream if needgi
        {
            float4 acc = make_float4(0.f,0.f,0.f,0.f);
            #pragma unroll
            for (int kk = 0; kk < 16; kk++){
                float c = curx[ks*16 + kk];
                acc.x += c*w1r[kk].x; acc.y += c*w1r[kk].y;
                acc.z += c*w1r[kk].z; acc.w += c*w1r[kk].w;
            }
            float4 ab = make_float4(0.f,0.f,0.f,0.f);
            if (needgi){
                const float* bwB = W1 + (EE + ks*16)*H1D + jg*4;
                #pragma unroll
                for (int kk = 0; kk < 16; kk++){
                    float4 wr = *(const float4*)(bwB + kk*H1D);
                    float c = curx[ks*16 + kk];
                    ab.x += c*wr.x; ab.y += c*wr.y; ab.z += c*wr.z; ab.w += c*wr.w;
                }
            }
            *(float4*)(dual + ks*H1D + jg*4) = acc;     // partF dead here
            if (needgi) *(float4*)(dualB + ks*H1D + jg*4) = ab;
        }
        __syncthreads();
        if (tid < H1D){
            float ssum = 0.f;
            #pragma unroll
            for (int kq = 0; kq < 8; kq++) ssum += dual[kq*H1D + tid];
            a_[tid] = ssum;
        } else if (needgi){
            int jj = tid - 256;
            float sb = 0.f;
            #pragma unroll
            for (int kq = 0; kq < 8; kq++) sb += dualB[kq*H1D + jj];
            g_G[i*H1D + jj] = sb;
            Grow[qi*256 + jj] = sb;
        }
        if (needgi) gdirty = 0;
        __syncthreads();
    } // steps

    // ---- early release: S4b writes (feat/upd/G[vsel]) are done ----
    __threadfence();
    __syncthreads();
    if (tid == 0) st_release(&g_done[i], 1);

    // ---- flush stale G[i] only if some j>i can read it ----
    if (gdirty && needany){
        {
            const float* bwB = W1 + (EE + ks*16)*H1D + jg*4;
            float4 acc = make_float4(0.f,0.f,0.f,0.f);
            #pragma unroll
            for (int kk = 0; kk < 16; kk++){
                float4 wr = *(const float4*)(bwB + kk*H1D);
                float c = curx[ks*16 + kk];
                acc.x += c*wr.x; acc.y += c*wr.y; acc.z += c*wr.z; acc.w += c*wr.w;
            }
            *(float4*)(dual + ks*H1D + jg*4) = acc;
        }
        __syncthreads();
        if (tid < H1D){
            float ssum = 0.f;
            #pragma unroll
            for (int kq = 0; kq < 8; kq++) ssum += dual[kq*H1D + tid];
            g_G[i*H1D + tid] = ssum;
        }
        __threadfence();
    }
    __syncthreads();
    if (tid == 0) st_release(&g_doneG[i], 1);

    // ---- out phase: wait conflicting j > i (early flag), write own row ----
    if (w == 0){
        unsigned pend = 0;
        #pragma unroll
        for (int q = 0; q < 4; q++){
            int j = lane + q*32;
            if (j > i && (((g_mL[j] & myL) | (g_mH[j] & myH)) != 0ull))
                pend |= 1u << q;
        }
        while (__ballot_sync(0xffffffffu, pend != 0u)){
            #pragma unroll
            for (int q = 0; q < 4; q++){
                if (pend & (1u << q)){
                    if (ld_acquire(&g_done[lane + q*32])) pend &= ~(1u << q);
                }
            }
        }
    }
    __syncthreads();
    if (tid < EE){
        int u  = __ldcg(&g_upd[i]);
        float f = __ldcg(&g_feat[i*EE + tid]);
        out[i*EE + tid] = u ? f : 0.f;
    }
}

// ---------------- launch ------------------------------------------------------
static const int DYN_SMEM = (32768 + 1024 + 4096 + 768 + 768 + 384 + 384
                             + 128 + 256 + 128 + 128 + 256 + 128 + 128
                             + 128 + 128 + 128) * (int)sizeof(float);

extern "C" void kernel_launch(void* const* d_in, const int* in_sizes, int n_in,
                              void* d_out, int out_size)
{
    const float* adj = (const float*)d_in[0];
    const float* fo  = (const float*)d_in[1];
    // d_in[2] = labels (unused)
    const float* We  = (const float*)d_in[3];
    const float* be  = (const float*)d_in[4];
    const float* W1  = (const float*)d_in[5];
    const float* b1  = (const float*)d_in[6];
    const float* W2  = (const float*)d_in[7];
    const float* b2  = (const float*)d_in[8];
    const float* wlk = (const float*)d_in[9];
    const float* blk = (const float*)d_in[10];
    const float* wac = (const float*)d_in[11];
    const float* bac = (const float*)d_in[12];
    float* out = (float*)d_out;

    cudaFuncSetAttribute(dataflow_kernel, cudaFuncAttributeMaxDynamicSharedMemorySize, DYN_SMEM);

    init_kernel<<<NN, 128>>>(fo, We, be, adj, W1);
    dataflow_kernel<<<NN, TPB, DYN_SMEM>>>(W1, W2, b1, b2, wlk, blk, wac, bac, be, out);
}

// round 10
// speedup vs baseline: 6.0304x; 1.0469x over previous
#include <cuda_runtime.h>

#define NN   128
#define FIN  512
#define EE   128
#define H1D  256
#define H2D  128
#define TPB  512

typedef unsigned long long ull;

__device__ __forceinline__ ull ffma2(ull a, ull b, ull c){
    ull d;
    asm("fma.rn.f32x2 %0, %1, %2, %3;" : "=l"(d) : "l"(a), "l"(b), "l"(c));
    return d;
}
__device__ __forceinline__ ull packff(float x){
    ull d; asm("mov.b64 %0, {%1, %2};" : "=l"(d) : "f"(x), "f"(x)); return d;
}
__device__ __forceinline__ int ld_acquire(const int* p){
    int v;
    asm volatile("ld.acquire.gpu.global.b32 %0, [%1];" : "=r"(v) : "l"(p) : "memory");
    return v;
}
__device__ __forceinline__ void red_release_add1(int* p){
    asm volatile("red.release.gpu.global.add.s32 [%0], 1;" :: "l"(p) : "memory");
}

// ---------------- persistent device state ----------------------------------
__device__ float g_P[NN*EE];
__device__ float g_feat0[NN*EE];
__device__ float g_A0[NN*H1D];
__device__ float g_G0[NN*H1D];
__device__ float g_G[NN*H1D];
__device__ float g_feat[NN*EE];
__device__ int   g_cand[NN*4];
__device__ int   g_ccnt[NN];
__device__ int   g_upd[NN];
__device__ int   g_rowcnt[NN];    // per-row finalization counter
__device__ ull   g_touchL[NN], g_touchH[NN];  // set of nodes touching row v
__device__ int   g_needany[NN];

// ---------------- fused init: one node per block (128 thr) ------------------
__global__ void init_kernel(const float* __restrict__ fo, const float* __restrict__ We,
                            const float* __restrict__ be, const float* __restrict__ adj,
                            const float* __restrict__ W1)
{
    __shared__ float fos[FIN];
    __shared__ float fs[EE];
    __shared__ unsigned bal[4], balc[4];
    const int i = blockIdx.x, e = threadIdx.x;     // 128 threads

    ((float4*)fos)[e] = ((const float4*)(fo + i*FIN))[e];
    unsigned b = __ballot_sync(0xffffffffu, adj[i*NN + e] != 0.0f);
    if ((e & 31) == 0) bal[e >> 5] = b;
    // touch column: p touches row i iff adj[p][i]!=0 or p==i
    unsigned bc = __ballot_sync(0xffffffffu, (adj[e*NN + i] != 0.0f) || (e == i));
    if ((e & 31) == 0) balc[e >> 5] = bc;
    int fl = (e > i) ? (adj[e*NN + i] != 0.0f) : 0;
    int any = __syncthreads_or(fl);
    if (e == 0) g_needany[i] = any;

    // P / feat0 (exact per-output f order)
    float s = 0.f;
    #pragma unroll 16
    for (int f = 0; f < FIN; f++) s += fos[f] * We[f*EE + e];
    g_P[i*EE+e] = s;
    float f0 = fmaxf(s + be[e], 0.f);
    g_feat0[i*EE+e] = f0;
    g_feat [i*EE+e] = f0;
    fs[e] = f0;

    if (e == 0) {
        g_upd[i]    = 0;
        g_rowcnt[i] = 0;
        g_touchL[i] = (ull)balc[0] | ((ull)balc[1] << 32);
        g_touchH[i] = (ull)balc[2] | ((ull)balc[3] << 32);
        int c = 0;
        for (int wq = 0; wq < 4; wq++){
            unsigned bb = bal[wq];
            while (bb){
                int bit = __ffs(bb) - 1; bb &= bb - 1;
                int vtx = wq*32 + bit;
                if (c < 4) g_cand[i*4 + c] = vtx;
                c++;
            }
        }
        if (c > 3) c = 3;                          // K=3 -> <=3 distinct
        g_ccnt[i] = c;
    }
    __syncthreads();

    // A0 / G0 / G (exact per-output k order; 2 j-outputs per thread)
    #pragma unroll
    for (int h = 0; h < 2; h++){
        int j = e + h*128;
        float st = 0.f, sb = 0.f;
        #pragma unroll 16
        for (int k = 0; k < EE; k++){
            float f = fs[k];
            st += f * W1[k*H1D + j];
            sb += f * W1[(EE+k)*H1D + j];
        }
        g_A0[i*H1D+j] = st;
        g_G0[i*H1D+j] = sb;
        g_G [i*H1D+j] = sb;
    }
}

// ---------------- S2: NPAIR row-pairs, W2 from smem --------------------------
template<int NPAIR>
__device__ __forceinline__ void s2_compute(const float* __restrict__ h1T,
                                           const float* __restrict__ W2s,
                                           float2* __restrict__ part,
                                           int kslab, int j0)
{
    ull accA[NPAIR], accB[NPAIR];
    #pragma unroll
    for (int p = 0; p < NPAIR; p++){ accA[p] = 0ull; accB[p] = 0ull; }
    #pragma unroll
    for (int kk = 0; kk < 32; kk++){
        int k = kslab*32 + kk;
        float2 wv = *(const float2*)(W2s + k*H2D + j0);
        ull wpa = packff(wv.x), wpb = packff(wv.y);
        if (NPAIR == 2){
            ulonglong2 hp = *(const ulonglong2*)(h1T + 4*k);
            accA[0] = ffma2(hp.x, wpa, accA[0]);
            accB[0] = ffma2(hp.x, wpb, accB[0]);
            accA[1] = ffma2(hp.y, wpa, accA[1]);
            accB[1] = ffma2(hp.y, wpb, accB[1]);
        } else {
            ull hx = *(const ull*)(h1T + 4*k);
            accA[0] = ffma2(hx, wpa, accA[0]);
            accB[0] = ffma2(hx, wpb, accB[0]);
        }
    }
    #pragma unroll
    for (int p = 0; p < NPAIR; p++){
        float2 fa, fb;
        asm("mov.b64 {%0,%1}, %2;" : "=f"(fa.x), "=f"(fa.y) : "l"(accA[p]));
        asm("mov.b64 {%0,%1}, %2;" : "=f"(fb.x), "=f"(fb.y) : "l"(accB[p]));
        part[(p*8 + kslab)*H2D + j0]     = fa;
        part[(p*8 + kslab)*H2D + j0 + 1] = fb;
    }
}

// ---------------- dataflow rollout: 128 CTAs, one node each ------------------
extern __shared__ float smx[];

__global__ void __launch_bounds__(TPB, 1) dataflow_kernel(
    const float* __restrict__ W1, const float* __restrict__ W2,
    const float* __restrict__ b1, const float* __restrict__ b2,
    const float* __restrict__ wlk, const float* __restrict__ blk,
    const float* __restrict__ wact, const float* __restrict__ bact,
    const float* __restrict__ be, float* __restrict__ out)
{
    float* base_ = smx;
    float*  W2s  = base_;  base_ += 32768;   // W2 [256k][128j]
    float*  h1T  = base_;  base_ += 1024;    // [k][4 slots]
    float*  partF= base_;  base_ += 4096;    // S2 partials; aliased by dual/dualB
    float*  Grow = base_;  base_ += 768;     // candidate G rows [3][256]
    float*  G0s  = base_;  base_ += 768;     // candidate G0 rows
    float*  Pvs  = base_;  base_ += 384;     // candidate P rows [3][128]
    float*  f0vs = base_;  base_ += 384;     // candidate feat0 rows
    float*  Pis  = base_;  base_ += 128;
    float*  a_   = base_;  base_ += 256;
    float*  curx = base_;  base_ += 128;
    float*  selP = base_;  base_ += 128;
    float*  b1s  = base_;  base_ += 256;
    float*  b2s  = base_;  base_ += 128;
    float*  wlks = base_;  base_ += 128;
    float*  wa0  = base_;  base_ += 128;
    float*  wa1  = base_;  base_ += 128;
    float*  bes  = base_;  base_ += 128;

    float2* part  = (float2*)partF;
    float*  dual  = partF;            // 2048 floats
    float*  dualB = partF + 2048;     // 2048 floats

    __shared__ float s_lk[4], s_a0[4], s_a1[4];

    const int i    = blockIdx.x;
    const int tid  = threadIdx.x;
    const int w    = tid >> 5;
    const int lane = tid & 31;
    const int kslab = w >> 1, jh = w & 1;
    const int j0 = jh*64 + lane*2;
    const int jg = tid & 63, ks = tid >> 6;

    // ---- pre-wait: constants, W2->smem, W1_top->regs, static prefetch ----
    if (tid < H1D) b1s[tid] = b1[tid];
    if (tid < H2D){ b2s[tid]=b2[tid]; wlks[tid]=wlk[tid];
                    wa0[tid]=wact[2*tid]; wa1[tid]=wact[2*tid+1]; }
    if (tid < EE){ bes[tid] = be[tid]; selP[tid] = 0.f; Pis[tid] = g_P[i*EE+tid]; }
    if (tid < H1D) a_[tid] = g_A0[i*H1D + tid];
    const float blkv = __ldg(blk), ba0v = __ldg(bact), ba1v = __ldg(bact+1);

    #pragma unroll
    for (int q = 0; q < 16; q++)
        ((float4*)W2s)[q*TPB + tid] = ((const float4*)W2)[q*TPB + tid];

    float4 w1r[16];
    #pragma unroll
    for (int kk = 0; kk < 16; kk++)
        w1r[kk] = *(const float4*)(W1 + (ks*16+kk)*H1D + jg*4);

    const int cc = g_ccnt[i];
    int candv[3];
    #pragma unroll
    for (int q = 0; q < 3; q++) candv[q] = (q < cc) ? g_cand[i*4+q] : -1;
    const int needany = g_needany[i];

    // prefix mask: bits < i
    ull mskL, mskH;
    if (i < 64){ mskL = (1ull << i) - 1ull; mskH = 0ull; }
    else       { mskL = ~0ull; mskH = (1ull << (i - 64)) - 1ull; }

    const ull tLi = g_touchL[i], tHi = g_touchH[i];
    const int expI = __popcll(tLi & mskL) + __popcll(tHi & mskH);
    const int totI = __popcll(tLi) + __popcll(tHi);
    int selfInCand = 0;
    #pragma unroll
    for (int q = 0; q < 3; q++) if (q < cc && candv[q] == i) selfInCand = 1;

    for (int t = tid; t < 768; t += TPB){
        int q = t >> 8, k = t & 255;
        if (q < cc) G0s[q*256+k] = g_G0[candv[q]*H1D + k];
    }
    if (tid < 384){
        int q = tid >> 7, e = tid & 127;
        if (q < cc){ Pvs[q*128+e] = g_P[candv[q]*EE+e];
                     f0vs[q*128+e] = g_feat0[candv[q]*EE+e]; }
    }

    // ---- wait for candidate rows to reach their prefix counts ----
    if (cc > 0){
        if (w == 0){
            int r = -1, ex = 0;
            if (lane < cc){
                r = candv[lane];
                ex = __popcll(g_touchL[r] & mskL) + __popcll(g_touchH[r] & mskH);
            }
            int pend = (r >= 0);
            while (__ballot_sync(0xffffffffu, pend)){
                if (pend && ld_acquire(&g_rowcnt[r]) >= ex) pend = 0;
            }
        }
        __syncthreads();   // rows ready + smem staging complete
    } else {
        __syncthreads();
    }

    // ---- per-thread uniform rollout state ----
    int aliveM = (1 << cc) - 1, na = cc;
    int done = 0, gdirty = 0, needgi = 0, qi = -1;
    int pub = 0;                       // candidate slots already published
    int rowiOK = selfInCand;           // own-row prefix satisfied?
    float cntf = 0.f;

    for (int step = 0; step < 3; step++){
        if (na == 0) break;

        int slots[4]; int ns = 0;
        #pragma unroll
        for (int q = 0; q < 3; q++) if ((aliveM >> q) & 1) slots[ns++] = q;
        slots[ns++] = -1;                       // sentinel last
        int npair = (ns + 1) >> 1;

        // S1: h1T[k][slot]
        {
            int k = tid & 255, hi = tid >> 8;
            float ak = a_[k] + b1s[k];
            #pragma unroll
            for (int h = 0; h < 2; h++){
                int s = hi*2 + h; float val = 0.f;
                if (s < ns){
                    int q = slots[s];
                    if (q < 0) val = fmaxf(ak, 0.f);
                    else {
                        int v = candv[q]; float gg;
                        if (step == 0){
                            gg = (v > 0) ? g_G[v*H1D + k] : 0.f;   // `if v>0` quirk
                            Grow[q*256 + k] = gg;
                        } else gg = (v > 0) ? Grow[q*256 + k] : 0.f;
                        val = fmaxf(ak + gg, 0.f);
                    }
                }
                h1T[k*4 + s] = val;
            }
        }
        __syncthreads();

        // S2
        if (npair == 2) s2_compute<2>(h1T, W2s, part, kslab, j0);
        else            s2_compute<1>(h1T, W2s, part, kslab, j0);
        __syncthreads();

        // S3: warp per slot
        if (w < ns){
            int pair = w >> 1, el = w & 1;
            float lk = 0.f, p0 = 0.f, p1 = 0.f;
            #pragma unroll
            for (int qq = 0; qq < 4; qq++){
                int j = lane + qq*32;
                float ssm = b2s[j];
                #pragma unroll
                for (int kq = 0; kq < 8; kq++){
                    float2 vv = part[(pair*8 + kq)*H2D + j];
                    ssm += el ? vv.y : vv.x;
                }
                float h = fmaxf(ssm, 0.f);
                lk += h*wlks[j]; p0 += h*wa0[j]; p1 += h*wa1[j];
            }
            #pragma unroll
            for (int off = 16; off; off >>= 1){
                lk += __shfl_xor_sync(0xffffffffu, lk, off);
                p0 += __shfl_xor_sync(0xffffffffu, p0, off);
                p1 += __shfl_xor_sync(0xffffffffu, p1, off);
            }
            if (lane == 0){ s_lk[w]=lk+blkv; s_a0[w]=p0+ba0v; s_a1[w]=p1+ba1v; }
        }
        __syncthreads();

        // Decision — all threads, uniform registers
        float best = -3.4028235e38f; int bs = -1;
        for (int s = 0; s < ns-1; s++){
            float l = s_lk[s];
            if (l > best){ best = l; bs = s; }
        }
        int vsel = 0, at = 0, qsel = -1, sel = 0; float denom = 1.f;
        if (s_lk[ns-1] > best){
            done = 1;
        } else {
            #pragma unroll
            for (int s = 0; s < 3; s++) if (s == bs) qsel = slots[s];
            vsel = candv[qsel];
            at = (s_a1[bs] > s_a0[bs]) ? 1 : 0;
            denom = cntf + (float)at + 1.0f;
            cntf += (float)at;
            aliveM &= ~(1 << qsel); na--; sel = 1;
            needgi = 0; qi = -1;
            #pragma unroll
            for (int q = 0; q < 3; q++)
                if (((aliveM >> q) & 1) && candv[q] == i){ needgi = 1; qi = q; }
            gdirty = (vsel == i) ? 0 : 1;
        }
        if (done) break;

        // deferred own-row wait: must precede first write to row i
        if (sel && !rowiOK){
            if (w == 0){
                while (ld_acquire(&g_rowcnt[i]) < expI) { }
            }
            __syncthreads();
            rowiOK = 1;
        }

        // S4b: apply updates (all-smem sources)
        {
            if (tid == 0){ g_upd[i] = 1; g_upd[vsel] = 1; }
            int grp = tid >> 7, e = tid & 127;
            if (grp == 0){
                float pv = Pvs[qsel*128+e], pi = Pis[e];
                float nx = fmaxf((selP[e] + (float)at*pv + pi)/denom + bes[e], 0.f);
                float f0v = f0vs[qsel*128+e];
                float fx = (vsel == i) ? f0v : nx;
                if (at) selP[e] += pv;
                g_feat[i*EE + e] = fx;
                curx[e] = fx;
            } else if (grp == 1){
                g_feat[vsel*EE + e] = f0vs[qsel*128+e];
            } else {
                int jj = tid - 256;
                g_G[vsel*H1D + jj] = G0s[qsel*256 + jj];
            }
        }
        __threadfence();           // order row writes before publish
        __syncthreads();
        if (tid == 0 && vsel != i) red_release_add1(&g_rowcnt[vsel]);
        if (vsel != i) pub |= 1 << qsel;

        if (na == 0) break;
        if (step >= 2) break;

        // S5: a = curx @ W1_top (registers); + G[i] bottom LDG stream if needgi
        {
            float4 acc = make_float4(0.f,0.f,0.f,0.f);
            #pragma unroll
            for (int kk = 0; kk < 16; kk++){
                float c = curx[ks*16 + kk];
                acc.x += c*w1r[kk].x; acc.y += c*w1r[kk].y;
                acc.z += c*w1r[kk].z; acc.w += c*w1r[kk].w;
            }
            float4 ab = make_float4(0.f,0.f,0.f,0.f);
            if (needgi){
                const float* bwB = W1 + (EE + ks*16)*H1D + jg*4;
                #pragma unroll
                for (int kk = 0; kk < 16; kk++){
                    float4 wr = *(const float4*)(bwB + kk*H1D);
                    float c = curx[ks*16 + kk];
                    ab.x += c*wr.x; ab.y += c*wr.y; ab.z += c*wr.z; ab.w += c*wr.w;
                }
            }
            *(float4*)(dual + ks*H1D + jg*4) = acc;     // partF dead here
            if (needgi) *(float4*)(dualB + ks*H1D + jg*4) = ab;
        }
        __syncthreads();
        if (tid < H1D){
            float ssum = 0.f;
            #pragma unroll
            for (int kq = 0; kq < 8; kq++) ssum += dual[kq*H1D + tid];
            a_[tid] = ssum;
        } else if (needgi){
            int jj = tid - 256;
            float sb = 0.f;
            #pragma unroll
            for (int kq = 0; kq < 8; kq++) sb += dualB[kq*H1D + jj];
            g_G[i*H1D + jj] = sb;
            Grow[qi*256 + jj] = sb;
        }
        if (needgi) gdirty = 0;
        __syncthreads();
    } // steps

    // ---- termination: publish untouched candidate rows ----
    __threadfence();
    __syncthreads();
    if (tid == 0){
        #pragma unroll
        for (int q = 0; q < 3; q++)
            if (q < cc && !((pub >> q) & 1) && candv[q] != i)
                red_release_add1(&g_rowcnt[candv[q]]);
    }

    // ---- flush stale G[i] only if some j>i can read it ----
    if (gdirty && needany){
        {
            const float* bwB = W1 + (EE + ks*16)*H1D + jg*4;
            float4 acc = make_float4(0.f,0.f,0.f,0.f);
            #pragma unroll
            for (int kk = 0; kk < 16; kk++){
                float4 wr = *(const float4*)(bwB + kk*H1D);
                float c = curx[ks*16 + kk];
                acc.x += c*wr.x; acc.y += c*wr.y; acc.z += c*wr.z; acc.w += c*wr.w;
            }
            *(float4*)(dual + ks*H1D + jg*4) = acc;
        }
        __syncthreads();
        if (tid < H1D){
            float ssum = 0.f;
            #pragma unroll
            for (int kq = 0; kq < 8; kq++) ssum += dual[kq*H1D + tid];
            g_G[i*H1D + tid] = ssum;
        }
        __threadfence();
    }
    __syncthreads();
    if (tid == 0) red_release_add1(&g_rowcnt[i]);   // own row final

    // ---- out phase: wait until every toucher of row i has finalized ----
    if (w == 0){
        while (ld_acquire(&g_rowcnt[i]) < totI) { }
    }
    __syncthreads();
    if (tid < EE){
        int u  = __ldcg(&g_upd[i]);
        float f = __ldcg(&g_feat[i*EE + tid]);
        out[i*EE + tid] = u ? f : 0.f;
    }
}

// ---------------- launch ------------------------------------------------------
static const int DYN_SMEM = (32768 + 1024 + 4096 + 768 + 768 + 384 + 384
                             + 128 + 256 + 128 + 128 + 256 + 128 + 128
                             + 128 + 128 + 128) * (int)sizeof(float);

extern "C" void kernel_launch(void* const* d_in, const int* in_sizes, int n_in,
                              void* d_out, int out_size)
{
    const float* adj = (const float*)d_in[0];
    const float* fo  = (const float*)d_in[1];
    // d_in[2] = labels (unused)
    const float* We  = (const float*)d_in[3];
    const float* be  = (const float*)d_in[4];
    const float* W1  = (const float*)d_in[5];
    const float* b1  = (const float*)d_in[6];
    const float* W2  = (const float*)d_in[7];
    const float* b2  = (const float*)d_in[8];
    const float* wlk = (const float*)d_in[9];
    const float* blk = (const float*)d_in[10];
    const float* wac = (const float*)d_in[11];
    const float* bac = (const float*)d_in[12];
    float* out = (float*)d_out;

    cudaFuncSetAttribute(dataflow_kernel, cudaFuncAttributeMaxDynamicSharedMemorySize, DYN_SMEM);

    init_kernel<<<NN, 128>>>(fo, We, be, adj, W1);
    dataflow_kernel<<<NN, TPB, DYN_SMEM>>>(W1, W2, b1, b2, wlk, blk, wac, bac, be, out);
}

// round 11
// speedup vs baseline: 7.0501x; 1.1691x over previous
#include <cuda_runtime.h>

#define NN   128
#define FIN  512
#define EE   128
#define H1D  256
#define H2D  128
#define TPB  512

typedef unsigned long long ull;

__device__ __forceinline__ ull ffma2(ull a, ull b, ull c){
    ull d;
    asm("fma.rn.f32x2 %0, %1, %2, %3;" : "=l"(d) : "l"(a), "l"(b), "l"(c));
    return d;
}
__device__ __forceinline__ ull packff(float x){
    ull d; asm("mov.b64 %0, {%1, %2};" : "=l"(d) : "f"(x), "f"(x)); return d;
}
__device__ __forceinline__ int ld_acquire(const int* p){
    int v;
    asm volatile("ld.acquire.gpu.global.b32 %0, [%1];" : "=r"(v) : "l"(p) : "memory");
    return v;
}
__device__ __forceinline__ void red_release_add1(int* p){
    asm volatile("red.release.gpu.global.add.s32 [%0], 1;" :: "l"(p) : "memory");
}

// ---------------- persistent device state ----------------------------------
__device__ float g_P[NN*EE];
__device__ float g_feat0[NN*EE];
__device__ float g_A0[NN*H1D];
__device__ float g_G0[NN*H1D];
__device__ float g_G[NN*H1D];
__device__ float g_feat[NN*EE];
__device__ int   g_cand[NN*4];
__device__ int   g_ccnt[NN];
__device__ int   g_upd[NN];
__device__ int   g_rowcnt[NN];    // per-row finalization counter
__device__ int   g_isG0[NN];      // 1 iff g_G[row] == G0[row]
__device__ ull   g_touchL[NN], g_touchH[NN];
__device__ int   g_needany[NN];

// ---------------- fused init: one node per block (128 thr) ------------------
__global__ void init_kernel(const float* __restrict__ fo, const float* __restrict__ We,
                            const float* __restrict__ be, const float* __restrict__ adj,
                            const float* __restrict__ W1)
{
    __shared__ float fos[FIN];
    __shared__ float fs[EE];
    __shared__ unsigned bal[4], balc[4];
    const int i = blockIdx.x, e = threadIdx.x;     // 128 threads

    ((float4*)fos)[e] = ((const float4*)(fo + i*FIN))[e];
    unsigned b = __ballot_sync(0xffffffffu, adj[i*NN + e] != 0.0f);
    if ((e & 31) == 0) bal[e >> 5] = b;
    unsigned bc = __ballot_sync(0xffffffffu, (adj[e*NN + i] != 0.0f) || (e == i));
    if ((e & 31) == 0) balc[e >> 5] = bc;
    int fl = (e > i) ? (adj[e*NN + i] != 0.0f) : 0;
    int any = __syncthreads_or(fl);
    if (e == 0) g_needany[i] = any;

    float s = 0.f;
    #pragma unroll 16
    for (int f = 0; f < FIN; f++) s += fos[f] * We[f*EE + e];
    g_P[i*EE+e] = s;
    float f0 = fmaxf(s + be[e], 0.f);
    g_feat0[i*EE+e] = f0;
    g_feat [i*EE+e] = f0;
    fs[e] = f0;

    if (e == 0) {
        g_upd[i]    = 0;
        g_rowcnt[i] = 0;
        g_isG0[i]   = 1;
        g_touchL[i] = (ull)balc[0] | ((ull)balc[1] << 32);
        g_touchH[i] = (ull)balc[2] | ((ull)balc[3] << 32);
        int c = 0;
        for (int wq = 0; wq < 4; wq++){
            unsigned bb = bal[wq];
            while (bb){
                int bit = __ffs(bb) - 1; bb &= bb - 1;
                int vtx = wq*32 + bit;
                if (c < 4) g_cand[i*4 + c] = vtx;
                c++;
            }
        }
        if (c > 3) c = 3;                          // K=3 -> <=3 distinct
        g_ccnt[i] = c;
    }
    __syncthreads();

    #pragma unroll
    for (int h = 0; h < 2; h++){
        int j = e + h*128;
        float st = 0.f, sb = 0.f;
        #pragma unroll 16
        for (int k = 0; k < EE; k++){
            float f = fs[k];
            st += f * W1[k*H1D + j];
            sb += f * W1[(EE+k)*H1D + j];
        }
        g_A0[i*H1D+j] = st;
        g_G0[i*H1D+j] = sb;
        g_G [i*H1D+j] = sb;
    }
}

// ---------------- S2: NPAIR row-pairs, W2 from smem --------------------------
template<int NPAIR>
__device__ __forceinline__ void s2_compute(const float* __restrict__ h1T,
                                           const float* __restrict__ W2s,
                                           float2* __restrict__ part,
                                           int kslab, int j0)
{
    ull accA[NPAIR], accB[NPAIR];
    #pragma unroll
    for (int p = 0; p < NPAIR; p++){ accA[p] = 0ull; accB[p] = 0ull; }
    #pragma unroll
    for (int kk = 0; kk < 32; kk++){
        int k = kslab*32 + kk;
        float2 wv = *(const float2*)(W2s + k*H2D + j0);
        ull wpa = packff(wv.x), wpb = packff(wv.y);
        if (NPAIR == 2){
            ulonglong2 hp = *(const ulonglong2*)(h1T + 4*k);
            accA[0] = ffma2(hp.x, wpa, accA[0]);
            accB[0] = ffma2(hp.x, wpb, accB[0]);
            accA[1] = ffma2(hp.y, wpa, accA[1]);
            accB[1] = ffma2(hp.y, wpb, accB[1]);
        } else {
            ull hx = *(const ull*)(h1T + 4*k);
            accA[0] = ffma2(hx, wpa, accA[0]);
            accB[0] = ffma2(hx, wpb, accB[0]);
        }
    }
    #pragma unroll
    for (int p = 0; p < NPAIR; p++){
        float2 fa, fb;
        asm("mov.b64 {%0,%1}, %2;" : "=f"(fa.x), "=f"(fa.y) : "l"(accA[p]));
        asm("mov.b64 {%0,%1}, %2;" : "=f"(fb.x), "=f"(fb.y) : "l"(accB[p]));
        part[(p*8 + kslab)*H2D + j0]     = fa;
        part[(p*8 + kslab)*H2D + j0 + 1] = fb;
    }
}

// ---------------- dataflow rollout: 128 CTAs, one node each ------------------
extern __shared__ float smx[];

__global__ void __launch_bounds__(TPB, 1) dataflow_kernel(
    const float* __restrict__ W1, const float* __restrict__ W2,
    const float* __restrict__ b1, const float* __restrict__ b2,
    const float* __restrict__ wlk, const float* __restrict__ blk,
    const float* __restrict__ wact, const float* __restrict__ bact,
    const float* __restrict__ be, float* __restrict__ out)
{
    float* base_ = smx;
    float*  W2s  = base_;  base_ += 32768;
    float*  h1T  = base_;  base_ += 1024;
    float*  partF= base_;  base_ += 4096;
    float*  Grow = base_;  base_ += 768;
    float*  G0s  = base_;  base_ += 768;
    float*  Pvs  = base_;  base_ += 384;
    float*  f0vs = base_;  base_ += 384;
    float*  Pis  = base_;  base_ += 128;
    float*  a_   = base_;  base_ += 256;
    float*  curx = base_;  base_ += 128;
    float*  selP = base_;  base_ += 128;
    float*  b1s  = base_;  base_ += 256;
    float*  b2s  = base_;  base_ += 128;
    float*  wlks = base_;  base_ += 128;
    float*  wa0  = base_;  base_ += 128;
    float*  wa1  = base_;  base_ += 128;
    float*  bes  = base_;  base_ += 128;

    float2* part  = (float2*)partF;
    float*  dual  = partF;
    float*  dualB = partF + 2048;

    __shared__ float s_lk[4], s_a0[4], s_a1[4];
    __shared__ int   s_flagok[3], s_allok;

    const int i    = blockIdx.x;
    const int tid  = threadIdx.x;
    const int w    = tid >> 5;
    const int lane = tid & 31;
    const int kslab = w >> 1, jh = w & 1;
    const int j0 = jh*64 + lane*2;
    const int jg = tid & 63, ks = tid >> 6;

    // ---- pre-wait staging ----
    if (tid < H1D) b1s[tid] = b1[tid];
    if (tid < H2D){ b2s[tid]=b2[tid]; wlks[tid]=wlk[tid];
                    wa0[tid]=wact[2*tid]; wa1[tid]=wact[2*tid+1]; }
    if (tid < EE){ bes[tid] = be[tid]; selP[tid] = 0.f; Pis[tid] = g_P[i*EE+tid]; }
    if (tid < H1D) a_[tid] = g_A0[i*H1D + tid];
    const float blkv = __ldg(blk), ba0v = __ldg(bact), ba1v = __ldg(bact+1);

    #pragma unroll
    for (int q = 0; q < 16; q++)
        ((float4*)W2s)[q*TPB + tid] = ((const float4*)W2)[q*TPB + tid];

    ull w1p[32];
    #pragma unroll
    for (int kk = 0; kk < 16; kk++){
        ulonglong2 t = *(const ulonglong2*)(W1 + (ks*16+kk)*H1D + jg*4);
        w1p[2*kk] = t.x; w1p[2*kk+1] = t.y;
    }

    const int cc = g_ccnt[i];
    int candv[3];
    #pragma unroll
    for (int q = 0; q < 3; q++) candv[q] = (q < cc) ? g_cand[i*4+q] : -1;
    const int needany = g_needany[i];

    ull mskL, mskH;
    if (i < 64){ mskL = (1ull << i) - 1ull; mskH = 0ull; }
    else       { mskL = ~0ull; mskH = (1ull << (i - 64)) - 1ull; }

    const ull tLi = g_touchL[i], tHi = g_touchH[i];
    const int expI = __popcll(tLi & mskL) + __popcll(tHi & mskH);
    const int totI = __popcll(tLi) + __popcll(tHi);
    int selfInCand = 0;
    #pragma unroll
    for (int q = 0; q < 3; q++) if (q < cc && candv[q] == i) selfInCand = 1;

    for (int t = tid; t < 768; t += TPB){
        int q = t >> 8, k = t & 255;
        if (q < cc) G0s[q*256+k] = g_G0[candv[q]*H1D + k];
    }
    if (tid < 384){
        int q = tid >> 7, e = tid & 127;
        if (q < cc){ Pvs[q*128+e] = g_P[candv[q]*EE+e];
                     f0vs[q*128+e] = g_feat0[candv[q]*EE+e]; }
    }
    __syncthreads();   // staging complete (G0s/a_/b1s ready for spec)

    // ---- SPECULATIVE step 0: compute S1+S2+S3 from static G0s ----
    if (cc > 0){
        int ns0 = cc + 1;
        {
            int k = tid & 255, hi = tid >> 8;
            float ak = a_[k] + b1s[k];
            #pragma unroll
            for (int h = 0; h < 2; h++){
                int s = hi*2 + h; float val = 0.f;
                if (s < ns0){
                    if (s < cc){
                        int v = candv[s];
                        float gg = (v > 0) ? G0s[s*256 + k] : 0.f;  // `if v>0` quirk
                        val = fmaxf(ak + gg, 0.f);
                    } else val = fmaxf(ak, 0.f);                     // sentinel
                }
                h1T[k*4 + s] = val;
            }
        }
        __syncthreads();
        if (ns0 >= 3) s2_compute<2>(h1T, W2s, part, kslab, j0);
        else          s2_compute<1>(h1T, W2s, part, kslab, j0);
        __syncthreads();
        if (w < ns0){
            int pair = w >> 1, el = w & 1;
            float lk = 0.f, p0 = 0.f, p1 = 0.f;
            #pragma unroll
            for (int qq = 0; qq < 4; qq++){
                int j = lane + qq*32;
                float ssm = b2s[j];
                #pragma unroll
                for (int kq = 0; kq < 8; kq++){
                    float2 vv = part[(pair*8 + kq)*H2D + j];
                    ssm += el ? vv.y : vv.x;
                }
                float h = fmaxf(ssm, 0.f);
                lk += h*wlks[j]; p0 += h*wa0[j]; p1 += h*wa1[j];
            }
            #pragma unroll
            for (int off = 16; off; off >>= 1){
                lk += __shfl_xor_sync(0xffffffffu, lk, off);
                p0 += __shfl_xor_sync(0xffffffffu, p0, off);
                p1 += __shfl_xor_sync(0xffffffffu, p1, off);
            }
            if (lane == 0){ s_lk[w]=lk+blkv; s_a0[w]=p0+ba0v; s_a1[w]=p1+ba1v; }
        }
    }

    // ---- wait for candidate rows to reach their prefix counts ----
    if (cc > 0){
        if (w == 0){
            int r = -1, ex = 0;
            if (lane < cc){
                r = candv[lane];
                ex = __popcll(g_touchL[r] & mskL) + __popcll(g_touchH[r] & mskH);
            }
            int pend = (r >= 0);
            while (__ballot_sync(0xffffffffu, pend)){
                if (pend && ld_acquire(&g_rowcnt[r]) >= ex) pend = 0;
            }
            // flags (acquire-ordered after rowcnt)
            int ok = 1;
            if (lane < cc){
                int v = candv[lane];
                ok = (v <= 0) ? 1 : ld_acquire(&g_isG0[v]);
                s_flagok[lane] = ok;
            }
            int all = __all_sync(0xffffffffu, ok);
            if (lane == 0) s_allok = all;
        }
        __syncthreads();

        if (s_allok){
            // spec hit: s_lk/s_a0/s_a1 valid; Grow = G0s for later steps
            for (int t = tid; t < 768; t += TPB){
                int q = t >> 8;
                if (q < cc) Grow[t] = G0s[t];
            }
        } else {
            // rebuild: Grow from g_G (flag 0) / G0s (flag 1), redo step-0 MLP
            for (int t = tid; t < 768; t += TPB){
                int q = t >> 8, k = t & 255;
                if (q < cc){
                    int v = candv[q];
                    float g = 0.f;
                    if (v > 0) g = s_flagok[q] ? G0s[t] : g_G[v*H1D + k];
                    Grow[t] = g;
                }
            }
            __syncthreads();
            int ns0 = cc + 1;
            {
                int k = tid & 255, hi = tid >> 8;
                float ak = a_[k] + b1s[k];
                #pragma unroll
                for (int h = 0; h < 2; h++){
                    int s = hi*2 + h; float val = 0.f;
                    if (s < ns0){
                        if (s < cc){
                            int v = candv[s];
                            float gg = (v > 0) ? Grow[s*256 + k] : 0.f;
                            val = fmaxf(ak + gg, 0.f);
                        } else val = fmaxf(ak, 0.f);
                    }
                    h1T[k*4 + s] = val;
                }
            }
            __syncthreads();
            if (ns0 >= 3) s2_compute<2>(h1T, W2s, part, kslab, j0);
            else          s2_compute<1>(h1T, W2s, part, kslab, j0);
            __syncthreads();
            if (w < ns0){
                int pair = w >> 1, el = w & 1;
                float lk = 0.f, p0 = 0.f, p1 = 0.f;
                #pragma unroll
                for (int qq = 0; qq < 4; qq++){
                    int j = lane + qq*32;
                    float ssm = b2s[j];
                    #pragma unroll
                    for (int kq = 0; kq < 8; kq++){
                        float2 vv = part[(pair*8 + kq)*H2D + j];
                        ssm += el ? vv.y : vv.x;
                    }
                    float h = fmaxf(ssm, 0.f);
                    lk += h*wlks[j]; p0 += h*wa0[j]; p1 += h*wa1[j];
                }
                #pragma unroll
                for (int off = 16; off; off >>= 1){
                    lk += __shfl_xor_sync(0xffffffffu, lk, off);
                    p0 += __shfl_xor_sync(0xffffffffu, p0, off);
                    p1 += __shfl_xor_sync(0xffffffffu, p1, off);
                }
                if (lane == 0){ s_lk[w]=lk+blkv; s_a0[w]=p0+ba0v; s_a1[w]=p1+ba1v; }
            }
        }
        __syncthreads();
    } else {
        __syncthreads();
    }

    // ---- per-thread uniform rollout state ----
    int aliveM = (1 << cc) - 1, na = cc;
    int done = 0, gdirty = 0, needgi = 0, qi = -1;
    int pub = 0, rowiOK = selfInCand, rowi_g0 = 1;
    float cntf = 0.f;

    for (int step = 0; step < 3; step++){
        if (na == 0) break;

        int slots[4]; int ns = 0;
        #pragma unroll
        for (int q = 0; q < 3; q++) if ((aliveM >> q) & 1) slots[ns++] = q;
        slots[ns++] = -1;                       // sentinel last
        int npair = (ns + 1) >> 1;

        if (step > 0){
            // S1 from Grow
            {
                int k = tid & 255, hi = tid >> 8;
                float ak = a_[k] + b1s[k];
                #pragma unroll
                for (int h = 0; h < 2; h++){
                    int s = hi*2 + h; float val = 0.f;
                    if (s < ns){
                        int q = slots[s];
                        if (q < 0) val = fmaxf(ak, 0.f);
                        else {
                            int v = candv[q];
                            float gg = (v > 0) ? Grow[q*256 + k] : 0.f;
                            val = fmaxf(ak + gg, 0.f);
                        }
                    }
                    h1T[k*4 + s] = val;
                }
            }
            __syncthreads();
            if (npair == 2) s2_compute<2>(h1T, W2s, part, kslab, j0);
            else            s2_compute<1>(h1T, W2s, part, kslab, j0);
            __syncthreads();
            if (w < ns){
                int pair = w >> 1, el = w & 1;
                float lk = 0.f, p0 = 0.f, p1 = 0.f;
                #pragma unroll
                for (int qq = 0; qq < 4; qq++){
                    int j = lane + qq*32;
                    float ssm = b2s[j];
                    #pragma unroll
                    for (int kq = 0; kq < 8; kq++){
                        float2 vv = part[(pair*8 + kq)*H2D + j];
                        ssm += el ? vv.y : vv.x;
                    }
                    float h = fmaxf(ssm, 0.f);
                    lk += h*wlks[j]; p0 += h*wa0[j]; p1 += h*wa1[j];
                }
                #pragma unroll
                for (int off = 16; off; off >>= 1){
                    lk += __shfl_xor_sync(0xffffffffu, lk, off);
                    p0 += __shfl_xor_sync(0xffffffffu, p0, off);
                    p1 += __shfl_xor_sync(0xffffffffu, p1, off);
                }
                if (lane == 0){ s_lk[w]=lk+blkv; s_a0[w]=p0+ba0v; s_a1[w]=p1+ba1v; }
            }
            __syncthreads();
        }

        // Decision — all threads, uniform registers
        float best = -3.4028235e38f; int bs = -1;
        for (int s = 0; s < ns-1; s++){
            float l = s_lk[s];
            if (l > best){ best = l; bs = s; }
        }
        int vsel = 0, at = 0, qsel = -1, sel = 0; float denom = 1.f;
        if (s_lk[ns-1] > best){
            done = 1;
        } else {
            #pragma unroll
            for (int s = 0; s < 3; s++) if (s == bs) qsel = slots[s];
            vsel = candv[qsel];
            at = (s_a1[bs] > s_a0[bs]) ? 1 : 0;
            denom = cntf + (float)at + 1.0f;
            cntf += (float)at;
            aliveM &= ~(1 << qsel); na--; sel = 1;
            needgi = 0; qi = -1;
            #pragma unroll
            for (int q = 0; q < 3; q++)
                if (((aliveM >> q) & 1) && candv[q] == i){ needgi = 1; qi = q; }
            gdirty = (vsel == i) ? 0 : 1;
        }
        if (done) break;

        // deferred own-row wait: must precede first write to row i
        if (sel && !rowiOK){
            if (w == 0){
                while (ld_acquire(&g_rowcnt[i]) < expI) { }
            }
            __syncthreads();
            rowiOK = 1;
        }

        // S4b: apply updates (all-smem sources)
        {
            if (tid == 0){
                g_upd[i] = 1; g_upd[vsel] = 1;
                if (vsel != i) g_isG0[vsel] = 1;     // reset -> G0
            }
            int grp = tid >> 7, e = tid & 127;
            if (grp == 0){
                float pv = Pvs[qsel*128+e], pi = Pis[e];
                float nx = fmaxf((selP[e] + (float)at*pv + pi)/denom + bes[e], 0.f);
                float f0v = f0vs[qsel*128+e];
                float fx = (vsel == i) ? f0v : nx;
                if (at) selP[e] += pv;
                g_feat[i*EE + e] = fx;
                curx[e] = fx;
            } else if (grp == 1){
                g_feat[vsel*EE + e] = f0vs[qsel*128+e];
            } else {
                int jj = tid - 256;
                g_G[vsel*H1D + jj] = G0s[qsel*256 + jj];
            }
        }
        __syncthreads();                               // cumulative release below
        if (tid == 0 && vsel != i) red_release_add1(&g_rowcnt[vsel]);
        if (vsel != i) pub |= 1 << qsel; else rowi_g0 = 1;

        if (na == 0) break;
        if (step >= 2) break;

        // S5: a = curx @ W1_top (packed regs); + G[i] bottom LDG stream if needgi
        {
            ull acc0 = 0, acc1 = 0;
            #pragma unroll
            for (int kk = 0; kk < 16; kk++){
                ull cp = packff(curx[ks*16 + kk]);
                acc0 = ffma2(w1p[2*kk],   cp, acc0);
                acc1 = ffma2(w1p[2*kk+1], cp, acc1);
            }
            ulonglong2 sb2; sb2.x = 0ull; sb2.y = 0ull;
            if (needgi){
                const float* bwB = W1 + (EE + ks*16)*H1D + jg*4;
                ull b0 = 0, b1u = 0;
                #pragma unroll
                for (int kk = 0; kk < 16; kk++){
                    ulonglong2 wrb = *(const ulonglong2*)(bwB + kk*H1D);
                    ull cp = packff(curx[ks*16 + kk]);
                    b0  = ffma2(wrb.x, cp, b0);
                    b1u = ffma2(wrb.y, cp, b1u);
                }
                sb2.x = b0; sb2.y = b1u;
            }
            ulonglong2 st2; st2.x = acc0; st2.y = acc1;
            *(ulonglong2*)(dual + ks*H1D + jg*4) = st2;
            if (needgi) *(ulonglong2*)(dualB + ks*H1D + jg*4) = sb2;
        }
        __syncthreads();
        if (tid < H1D){
            float ssum = 0.f;
            #pragma unroll
            for (int kq = 0; kq < 8; kq++) ssum += dual[kq*H1D + tid];
            a_[tid] = ssum;
        } else if (needgi){
            int jj = tid - 256;
            float sb = 0.f;
            #pragma unroll
            for (int kq = 0; kq < 8; kq++) sb += dualB[kq*H1D + jj];
            g_G[i*H1D + jj] = sb;
            Grow[qi*256 + jj] = sb;
        }
        if (needgi){ gdirty = 0; rowi_g0 = 0; }
        __syncthreads();
    } // steps

    // ---- termination: publish untouched candidate rows ----
    __syncthreads();
    if (tid == 0){
        #pragma unroll
        for (int q = 0; q < 3; q++)
            if (q < cc && !((pub >> q) & 1) && candv[q] != i)
                red_release_add1(&g_rowcnt[candv[q]]);
    }

    // ---- flush stale G[i] only if some j>i can read it ----
    if (gdirty && needany){
        {
            const float* bwB = W1 + (EE + ks*16)*H1D + jg*4;
            ull b0 = 0, b1u = 0;
            #pragma unroll
            for (int kk = 0; kk < 16; kk++){
                ulonglong2 wrb = *(const ulonglong2*)(bwB + kk*H1D);
                ull cp = packff(curx[ks*16 + kk]);
                b0  = ffma2(wrb.x, cp, b0);
                b1u = ffma2(wrb.y, cp, b1u);
            }
            ulonglong2 st2; st2.x = b0; st2.y = b1u;
            *(ulonglong2*)(dual + ks*H1D + jg*4) = st2;
        }
        __syncthreads();
        if (tid < H1D){
            float ssum = 0.f;
            #pragma unroll
            for (int kq = 0; kq < 8; kq++) ssum += dual[kq*H1D + tid];
            g_G[i*H1D + tid] = ssum;
        }
        rowi_g0 = 0;
    }
    __syncthreads();
    if (tid == 0){
        g_isG0[i] = rowi_g0;
        red_release_add1(&g_rowcnt[i]);   // own row final
    }

    // ---- out phase: wait until every toucher of row i has finalized ----
    if (w == 0){
        while (ld_acquire(&g_rowcnt[i]) < totI) { }
    }
    __syncthreads();
    if (tid < EE){
        int u  = __ldcg(&g_upd[i]);
        float f = __ldcg(&g_feat[i*EE + tid]);
        out[i*EE + tid] = u ? f : 0.f;
    }
}

// ---------------- launch ------------------------------------------------------
static const int DYN_SMEM = (32768 + 1024 + 4096 + 768 + 768 + 384 + 384
                             + 128 + 256 + 128 + 128 + 256 + 128 + 128
                             + 128 + 128 + 128) * (int)sizeof(float);

extern "C" void kernel_launch(void* const* d_in, const int* in_sizes, int n_in,
                              void* d_out, int out_size)
{
    const float* adj = (const float*)d_in[0];
    const float* fo  = (const float*)d_in[1];
    // d_in[2] = labels (unused)
    const float* We  = (const float*)d_in[3];
    const float* be  = (const float*)d_in[4];
    const float* W1  = (const float*)d_in[5];
    const float* b1  = (const float*)d_in[6];
    const float* W2  = (const float*)d_in[7];
    const float* b2  = (const float*)d_in[8];
    const float* wlk = (const float*)d_in[9];
    const float* blk = (const float*)d_in[10];
    const float* wac = (const float*)d_in[11];
    const float* bac = (const float*)d_in[12];
    float* out = (float*)d_out;

    cudaFuncSetAttribute(dataflow_kernel, cudaFuncAttributeMaxDynamicSharedMemorySize, DYN_SMEM);

    init_kernel<<<NN, 128>>>(fo, We, be, adj, W1);
    dataflow_kernel<<<NN, TPB, DYN_SMEM>>>(W1, W2, b1, b2, wlk, blk, wac, bac, be, out);
}